// round 1
// baseline (speedup 1.0000x reference)
#include <cuda_runtime.h>
#include <cuda_bf16.h>
#include <math.h>

// Problem constants
#define B_ 8192
#define F_ 1024
#define U_ 512
#define O_ 3
#define A_ 6
#define H_ 4
#define HD_ 128

// ---------------------------------------------------------------------------
// Scratch (device globals — no allocation allowed)
// ---------------------------------------------------------------------------
__device__ float g_cat[(size_t)B_ * 2 * U_];        // [B, 2U]: [agent_latent | attn_out]
__device__ float g_opp_lat[(size_t)O_ * B_ * U_];   // [O,B,U]
__device__ float g_q[(size_t)B_ * U_];
__device__ float g_k[(size_t)O_ * B_ * U_];
__device__ float g_v[(size_t)O_ * B_ * U_];
__device__ float g_attn[(size_t)B_ * U_];
__device__ float g_agent_head[(size_t)B_ * U_];
__device__ float g_opp_heads[(size_t)O_ * B_ * U_];

// ---------------------------------------------------------------------------
// Tiled fp32 GEMM: C[M,N] = act((A[M,K] @ W[N,K]^T + bias[N]) * scale)
// A row-major (lda), W row-major (ldw, K inner), C row-major (ldc).
// Requires M%128==0, N%128==0, K%16==0 (true for all big GEMMs here).
// ---------------------------------------------------------------------------
#define BM 128
#define BN 128
#define BK 16
#define TM 8
#define TN 8

template <bool ELU>
__global__ __launch_bounds__(256, 2)
void gemm_kernel(const float* __restrict__ A, int lda,
                 const float* __restrict__ W, int ldw,
                 const float* __restrict__ bias,
                 float* __restrict__ C, int ldc,
                 int K, float scale)
{
    __shared__ float As[BK][BM];
    __shared__ float Bs[BK][BN];

    const int tid = threadIdx.x;
    const int block_m = blockIdx.y * BM;
    const int block_n = blockIdx.x * BN;

    const int tx = tid % 16;  // n dimension
    const int ty = tid / 16;  // m dimension

    // loader mapping: 64 rows per pass, 4 float4 per row of 16
    const int lrow = tid >> 2;          // 0..63
    const int lcol = (tid & 3) * 4;     // 0,4,8,12

    const float* Aptr = A + (size_t)block_m * lda;
    const float* Wptr = W + (size_t)block_n * ldw;

    float acc[TM][TN];
#pragma unroll
    for (int i = 0; i < TM; i++)
#pragma unroll
        for (int j = 0; j < TN; j++) acc[i][j] = 0.f;

    for (int k0 = 0; k0 < K; k0 += BK) {
#pragma unroll
        for (int r = 0; r < BM; r += 64) {
            float4 va = *(const float4*)(Aptr + (size_t)(lrow + r) * lda + k0 + lcol);
            As[lcol + 0][lrow + r] = va.x;
            As[lcol + 1][lrow + r] = va.y;
            As[lcol + 2][lrow + r] = va.z;
            As[lcol + 3][lrow + r] = va.w;
        }
#pragma unroll
        for (int r = 0; r < BN; r += 64) {
            float4 vb = *(const float4*)(Wptr + (size_t)(lrow + r) * ldw + k0 + lcol);
            Bs[lcol + 0][lrow + r] = vb.x;
            Bs[lcol + 1][lrow + r] = vb.y;
            Bs[lcol + 2][lrow + r] = vb.z;
            Bs[lcol + 3][lrow + r] = vb.w;
        }
        __syncthreads();

#pragma unroll
        for (int k = 0; k < BK; k++) {
            float a[TM], b[TN];
#pragma unroll
            for (int i = 0; i < TM; i++) a[i] = As[k][ty * TM + i];
#pragma unroll
            for (int j = 0; j < TN; j++) b[j] = Bs[k][tx * TN + j];
#pragma unroll
            for (int i = 0; i < TM; i++)
#pragma unroll
                for (int j = 0; j < TN; j++)
                    acc[i][j] = fmaf(a[i], b[j], acc[i][j]);
        }
        __syncthreads();
    }

#pragma unroll
    for (int i = 0; i < TM; i++) {
        const size_t m = block_m + ty * TM + i;
#pragma unroll
        for (int j = 0; j < TN; j++) {
            const int n = block_n + tx * TN + j;
            float val = (acc[i][j] + bias[n]) * scale;
            if (ELU) val = val > 0.f ? val : expm1f(val);
            C[m * ldc + n] = val;
        }
    }
}

// ---------------------------------------------------------------------------
// Attention: per-b block (128 threads = 4 warps, one per head).
// q pre-scaled by 1/sqrt(HD). scores over O=3, softmax, weighted V, plus
// per-(b,o) influence = mean over heads of w.
// ---------------------------------------------------------------------------
__global__ void attention_kernel(const float* __restrict__ q,
                                 const float* __restrict__ k,
                                 const float* __restrict__ v,
                                 float* __restrict__ attn,
                                 float* __restrict__ infl)
{
    const int b = blockIdx.x;
    const int tid = threadIdx.x;
    const int h = tid >> 5;
    const int lane = tid & 31;
    __shared__ float sw[H_][O_];

    const size_t base = (size_t)b * U_ + (size_t)h * HD_;
    const float4 qv = *(const float4*)(q + base + lane * 4);

    float s[O_];
#pragma unroll
    for (int o = 0; o < O_; o++) {
        const size_t kb = (size_t)o * B_ * U_ + base;
        const float4 kv = *(const float4*)(k + kb + lane * 4);
        float d = qv.x * kv.x + qv.y * kv.y + qv.z * kv.z + qv.w * kv.w;
#pragma unroll
        for (int off = 16; off > 0; off >>= 1)
            d += __shfl_xor_sync(0xffffffffu, d, off);
        s[o] = d;
    }

    const float m = fmaxf(s[0], fmaxf(s[1], s[2]));
    const float e0 = expf(s[0] - m), e1 = expf(s[1] - m), e2 = expf(s[2] - m);
    const float inv = 1.f / (e0 + e1 + e2);
    const float w0 = e0 * inv, w1 = e1 * inv, w2 = e2 * inv;

    float4 a = make_float4(0.f, 0.f, 0.f, 0.f);
    const float w[O_] = {w0, w1, w2};
#pragma unroll
    for (int o = 0; o < O_; o++) {
        const size_t vb = (size_t)o * B_ * U_ + base;
        const float4 vv = *(const float4*)(v + vb + lane * 4);
        a.x = fmaf(w[o], vv.x, a.x);
        a.y = fmaf(w[o], vv.y, a.y);
        a.z = fmaf(w[o], vv.z, a.z);
        a.w = fmaf(w[o], vv.w, a.w);
    }
    *(float4*)(attn + base + lane * 4) = a;

    if (lane == 0) {
        sw[h][0] = w0; sw[h][1] = w1; sw[h][2] = w2;
    }
    __syncthreads();
    if (tid < O_)
        infl[(size_t)b * O_ + tid] =
            0.25f * (sw[0][tid] + sw[1][tid] + sw[2][tid] + sw[3][tid]);
}

// ---------------------------------------------------------------------------
// Skinny heads: out[b*ostride + n] = A[b]·W[n] + bias[n]   (N in {1,6})
// ---------------------------------------------------------------------------
__global__ void skinny_kernel(const float* __restrict__ A, int lda,
                              const float* __restrict__ W, int ldw,
                              const float* __restrict__ bias,
                              float* __restrict__ out, int ostride,
                              int M, int N, int K)
{
    const int idx = blockIdx.x * blockDim.x + threadIdx.x;
    if (idx >= M * N) return;
    const int b = idx / N;
    const int n = idx - b * N;
    const float4* a4 = (const float4*)(A + (size_t)b * lda);
    const float4* w4 = (const float4*)(W + (size_t)n * ldw);
    float acc = 0.f;
    const int K4 = K >> 2;
    for (int kk = 0; kk < K4; kk++) {
        const float4 av = a4[kk];
        const float4 wv = w4[kk];
        acc += av.x * wv.x + av.y * wv.y + av.z * wv.z + av.w * wv.w;
    }
    out[(size_t)b * ostride + n] = acc + bias[n];
}

// ---------------------------------------------------------------------------
extern "C" void kernel_launch(void* const* d_in, const int* in_sizes, int n_in,
                              void* d_out, int out_size)
{
    const float* features = (const float*)d_in[0];
    const float* W_al = (const float*)d_in[1];
    const float* b_al = (const float*)d_in[2];
    const float* W_in = (const float*)d_in[3];
    const float* b_in = (const float*)d_in[4];
    const float* W_out = (const float*)d_in[5];
    const float* b_out = (const float*)d_in[6];
    const float* W_ah = (const float*)d_in[7];
    const float* b_ah = (const float*)d_in[8];
    const float* W_ap = (const float*)d_in[9];
    const float* b_ap = (const float*)d_in[10];
    const float* W_av = (const float*)d_in[11];
    const float* b_av = (const float*)d_in[12];
    const float* W_ol = (const float*)d_in[13];
    const float* b_ol = (const float*)d_in[14];
    const float* W_oh = (const float*)d_in[15];
    const float* b_oh = (const float*)d_in[16];
    const float* W_op = (const float*)d_in[17];
    const float* b_op = (const float*)d_in[18];
    const float* W_ov = (const float*)d_in[19];
    const float* b_ov = (const float*)d_in[20];

    float* out = (float*)d_out;

    float *cat, *opp_lat, *q, *k, *v, *attn, *agent_head, *opp_heads;
    cudaGetSymbolAddress((void**)&cat, g_cat);
    cudaGetSymbolAddress((void**)&opp_lat, g_opp_lat);
    cudaGetSymbolAddress((void**)&q, g_q);
    cudaGetSymbolAddress((void**)&k, g_k);
    cudaGetSymbolAddress((void**)&v, g_v);
    cudaGetSymbolAddress((void**)&attn, g_attn);
    cudaGetSymbolAddress((void**)&agent_head, g_agent_head);
    cudaGetSymbolAddress((void**)&opp_heads, g_opp_heads);

    const size_t BU = (size_t)B_ * U_;
    const float qscale = 0.08838834764831845f;  // 1/sqrt(128)

    // output layout (concatenated, fp32):
    float* out_agent_policy = out;                                  // [B, 6]
    float* out_agent_value  = out + (size_t)B_ * A_;                // [B, 1]
    float* out_opp_policy   = out_agent_value + B_;                 // [B, O, A]
    float* out_opp_value    = out_opp_policy + (size_t)B_ * O_ * A_;// [B, O, 1]
    float* out_infl         = out_opp_value + (size_t)B_ * O_;      // [B, O]

    const dim3 blk(256);
    const dim3 gU(U_ / BN, B_ / BM);

    // 1) agent_latent -> cat[:, :U]
    gemm_kernel<true><<<gU, blk>>>(features, F_, W_al, F_, b_al,
                                   cat, 2 * U_, F_, 1.f);
    // 2) opp_lat[o]
    for (int o = 0; o < O_; o++)
        gemm_kernel<true><<<gU, blk>>>(features, F_, W_ol + (size_t)o * U_ * F_, F_,
                                       b_ol + o * U_, opp_lat + (size_t)o * BU, U_,
                                       F_, 1.f);
    // 3) q (pre-scaled)
    gemm_kernel<false><<<gU, blk>>>(cat, 2 * U_, W_in, U_, b_in,
                                    q, U_, U_, qscale);
    // 4) k[o], v[o]
    for (int o = 0; o < O_; o++)
        gemm_kernel<false><<<gU, blk>>>(opp_lat + (size_t)o * BU, U_,
                                        W_in + (size_t)U_ * U_, U_, b_in + U_,
                                        k + (size_t)o * BU, U_, U_, 1.f);
    for (int o = 0; o < O_; o++)
        gemm_kernel<false><<<gU, blk>>>(opp_lat + (size_t)o * BU, U_,
                                        W_in + (size_t)2 * U_ * U_, U_, b_in + 2 * U_,
                                        v + (size_t)o * BU, U_, U_, 1.f);
    // 5) attention + influences
    attention_kernel<<<B_, 128>>>(q, k, v, attn, out_infl);
    // 6) attn_out -> cat[:, U:]
    gemm_kernel<false><<<gU, blk>>>(attn, U_, W_out, U_, b_out,
                                    cat + U_, 2 * U_, U_, 1.f);
    // 7) agent_head
    gemm_kernel<true><<<gU, blk>>>(cat, 2 * U_, W_ah, 2 * U_, b_ah,
                                   agent_head, U_, 2 * U_, 1.f);
    // 8) agent policy / value
    skinny_kernel<<<(B_ * A_ + 255) / 256, 256>>>(agent_head, U_, W_ap, U_, b_ap,
                                                  out_agent_policy, A_, B_, A_, U_);
    skinny_kernel<<<(B_ + 255) / 256, 256>>>(agent_head, U_, W_av, U_, b_av,
                                             out_agent_value, 1, B_, 1, U_);
    // 9) opp_heads[o]
    for (int o = 0; o < O_; o++)
        gemm_kernel<true><<<gU, blk>>>(opp_lat + (size_t)o * BU, U_,
                                       W_oh + (size_t)o * U_ * U_, U_, b_oh + o * U_,
                                       opp_heads + (size_t)o * BU, U_, U_, 1.f);
    // 10) opponent policies / values
    for (int o = 0; o < O_; o++) {
        skinny_kernel<<<(B_ * A_ + 255) / 256, 256>>>(
            opp_heads + (size_t)o * BU, U_, W_op + (size_t)o * A_ * U_, U_,
            b_op + o * A_, out_opp_policy + o * A_, O_ * A_, B_, A_, U_);
        skinny_kernel<<<(B_ + 255) / 256, 256>>>(
            opp_heads + (size_t)o * BU, U_, W_ov + (size_t)o * U_, U_,
            b_ov + o, out_opp_value + o, O_, B_, 1, U_);
    }
}

// round 3
// speedup vs baseline: 2.1002x; 2.1002x over previous
#include <cuda_runtime.h>
#include <cuda_bf16.h>
#include <math.h>
#include <stdint.h>

// Problem constants
#define B_ 8192
#define F_ 1024
#define U_ 512
#define O_ 3
#define A_ 6
#define H_ 4
#define HD_ 128

typedef __nv_bfloat16 bf16;

// ===========================================================================
// Scratch (device globals) — 16B-aligned for cp.async / vector ops
// ===========================================================================
__device__ __align__(128) bf16  g_feat_hi[(size_t)B_ * F_], g_feat_lo[(size_t)B_ * F_];
__device__ __align__(128) bf16  g_cat_hi[(size_t)B_ * 2 * U_], g_cat_lo[(size_t)B_ * 2 * U_];
__device__ __align__(128) bf16  g_opp_hi[(size_t)O_ * B_ * U_], g_opp_lo[(size_t)O_ * B_ * U_];
__device__ __align__(128) float g_q[(size_t)B_ * U_];
__device__ __align__(128) float g_k[(size_t)O_ * B_ * U_];
__device__ __align__(128) float g_v[(size_t)O_ * B_ * U_];
__device__ __align__(128) bf16  g_attn_hi[(size_t)B_ * U_], g_attn_lo[(size_t)B_ * U_];
__device__ __align__(128) float g_ah[(size_t)B_ * U_];
__device__ __align__(128) float g_oh[(size_t)O_ * B_ * U_];
// weight hi/lo
__device__ __align__(128) bf16 g_Wal_hi[(size_t)U_ * F_],      g_Wal_lo[(size_t)U_ * F_];
__device__ __align__(128) bf16 g_Win_hi[(size_t)3 * U_ * U_],  g_Win_lo[(size_t)3 * U_ * U_];
__device__ __align__(128) bf16 g_Wout_hi[(size_t)U_ * U_],     g_Wout_lo[(size_t)U_ * U_];
__device__ __align__(128) bf16 g_Wah_hi[(size_t)U_ * 2 * U_],  g_Wah_lo[(size_t)U_ * 2 * U_];
__device__ __align__(128) bf16 g_Wol_hi[(size_t)O_ * U_ * F_], g_Wol_lo[(size_t)O_ * U_ * F_];
__device__ __align__(128) bf16 g_Woh_hi[(size_t)O_ * U_ * U_], g_Woh_lo[(size_t)O_ * U_ * U_];

// ===========================================================================
// small PTX helpers (all valid on plain compute_103 target)
// ===========================================================================
__device__ __forceinline__ uint32_t smem_u32(const void* p) {
    uint32_t a;
    asm("{ .reg .u64 t; cvta.to.shared.u64 t, %1; cvt.u32.u64 %0, t; }"
        : "=r"(a) : "l"(p));
    return a;
}
__device__ __forceinline__ void cp16(uint32_t s, const void* g) {
    asm volatile("cp.async.cg.shared.global [%0], [%1], 16;" :: "r"(s), "l"(g));
}
#define CP_COMMIT() asm volatile("cp.async.commit_group;" ::: "memory")
#define CP_WAIT0()  asm volatile("cp.async.wait_group 0;" ::: "memory")

__device__ __forceinline__ void ldsm4(uint32_t* r, uint32_t addr) {
    asm volatile("ldmatrix.sync.aligned.m8n8.x4.shared.b16 {%0,%1,%2,%3}, [%4];"
                 : "=r"(r[0]), "=r"(r[1]), "=r"(r[2]), "=r"(r[3]) : "r"(addr));
}
__device__ __forceinline__ void mma_bf16(float* c, const uint32_t* a, const uint32_t* b) {
    asm volatile("mma.sync.aligned.m16n8k16.row.col.f32.bf16.bf16.f32 "
                 "{%0,%1,%2,%3}, {%4,%5,%6,%7}, {%8,%9}, {%0,%1,%2,%3};"
                 : "+f"(c[0]), "+f"(c[1]), "+f"(c[2]), "+f"(c[3])
                 : "r"(a[0]), "r"(a[1]), "r"(a[2]), "r"(a[3]),
                   "r"(b[0]), "r"(b[1]));
}

// ===========================================================================
// fp32 -> bf16 hi/lo split (vectorized by 4)
// ===========================================================================
__global__ void convert_split(const float* __restrict__ src,
                              bf16* __restrict__ hi, bf16* __restrict__ lo, int n4)
{
    int i = blockIdx.x * blockDim.x + threadIdx.x;
    if (i >= n4) return;
    float4 x = ((const float4*)src)[i];
    bf16 h[4], l[4];
    float xs[4] = {x.x, x.y, x.z, x.w};
#pragma unroll
    for (int j = 0; j < 4; j++) {
        h[j] = __float2bfloat16_rn(xs[j]);
        l[j] = __float2bfloat16_rn(xs[j] - __bfloat162float(h[j]));
    }
    ((uint2*)hi)[i] = *(uint2*)h;
    ((uint2*)lo)[i] = *(uint2*)l;
}

// ===========================================================================
// Split-bf16 HMMA GEMM: C[M,N] = act(((Ah+Al) @ (Wh+Wl)^T + bias) * scale)
// CTA 128x128, 256 thr (8 warps = 4Mx2N, warp tile 32x64), K stage = 32.
// SMEM stage layout: 4 components (Ahi,Alo,Whi,Wlo), each 128 rows x 80B.
// ===========================================================================
#define MT 128
#define NT 128
#define KB 32
#define RSTRIDE 80                       // bytes per SMEM row (32 bf16 + pad)
#define COMP_BYTES (128 * RSTRIDE)       // 10240
#define OFF_AH 0
#define OFF_AL COMP_BYTES
#define OFF_WH (2 * COMP_BYTES)
#define OFF_WL (3 * COMP_BYTES)
#define STG_BYTES (4 * COMP_BYTES)       // 40960
#define GEMM_SMEM (1024 + 2 * STG_BYTES) // 82944

__device__ __forceinline__ void load_stage_async(
    uint32_t st, int tid,
    const bf16* __restrict__ Ahi, const bf16* __restrict__ Alo, int lda, int mtile,
    const bf16* __restrict__ Whi, const bf16* __restrict__ Wlo, int ldw, int ntile,
    int k0)
{
#pragma unroll
    for (int i = 0; i < 2; i++) {
        int idx = tid + i * 256;        // 0..511
        int r = idx >> 2, c = idx & 3;
        uint32_t so = (uint32_t)(r * RSTRIDE + c * 16);
        size_t ga = (size_t)(mtile + r) * lda + k0 + c * 8;
        size_t gw = (size_t)(ntile + r) * ldw + k0 + c * 8;
        cp16(st + OFF_AH + so, Ahi + ga);
        cp16(st + OFF_AL + so, Alo + ga);
        cp16(st + OFF_WH + so, Whi + gw);
        cp16(st + OFF_WL + so, Wlo + gw);
    }
    CP_COMMIT();
}

template <bool ELU_, bool WF32, bool WBF16>
__global__ void __launch_bounds__(256, 1)
gemm_mma(const bf16* __restrict__ Ahi, const bf16* __restrict__ Alo, int lda,
         const bf16* __restrict__ Whi, const bf16* __restrict__ Wlo, int ldw,
         const float* __restrict__ bias, float scale,
         float* __restrict__ Cf, int ldcf,
         bf16* __restrict__ Chi, bf16* __restrict__ Clo, int ldcb,
         int K)
{
    extern __shared__ __align__(128) char smem[];
    float* bias_s = (float*)smem;
    const uint32_t st0 = smem_u32(smem + 1024);
    const uint32_t st1 = st0 + STG_BYTES;

    const int tid = threadIdx.x, lane = tid & 31, wid = tid >> 5;
    const int wm = wid & 3, wn = wid >> 2;
    const int mtile = blockIdx.y * MT;
    const int ntile = blockIdx.x * NT;

    if (tid < NT) bias_s[tid] = bias[ntile + tid];

    float acc[2][8][4];
#pragma unroll
    for (int i = 0; i < 2; i++)
#pragma unroll
        for (int j = 0; j < 8; j++)
#pragma unroll
            for (int t = 0; t < 4; t++) acc[i][j][t] = 0.f;

    const int nc = K / KB;

    load_stage_async(st0, tid, Ahi, Alo, lda, mtile, Whi, Wlo, ldw, ntile, 0);
    CP_WAIT0();
    __syncthreads();

    // precomputed ldmatrix intra-tile offsets
    const uint32_t a_row = (uint32_t)(lane & 15);
    const uint32_t a_koff = (uint32_t)((lane >> 4) * 16);
    const uint32_t b_row = (uint32_t)(((lane >> 4) * 8) + (lane & 7));
    const uint32_t b_koff = (uint32_t)(((lane >> 3) & 1) * 16);

    for (int c = 0; c < nc; ++c) {
        const uint32_t cur = (c & 1) ? st1 : st0;
        if (c + 1 < nc)
            load_stage_async((c & 1) ? st0 : st1, tid,
                             Ahi, Alo, lda, mtile, Whi, Wlo, ldw, ntile,
                             (c + 1) * KB);
#pragma unroll
        for (int kc = 0; kc < 2; kc++) {
            uint32_t ah[2][4], al[2][4], bh[4][4], bl[4][4];
#pragma unroll
            for (int mt = 0; mt < 2; mt++) {
                uint32_t row = wm * 32 + mt * 16 + a_row;
                uint32_t off = row * RSTRIDE + kc * 32 + a_koff;
                ldsm4(ah[mt], cur + OFF_AH + off);
                ldsm4(al[mt], cur + OFF_AL + off);
            }
#pragma unroll
            for (int q = 0; q < 4; q++) {
                uint32_t row = wn * 64 + q * 16 + b_row;
                uint32_t off = row * RSTRIDE + kc * 32 + b_koff;
                ldsm4(bh[q], cur + OFF_WH + off);
                ldsm4(bl[q], cur + OFF_WL + off);
            }
            // pass-major order: 16 independent accumulators per pass
#pragma unroll
            for (int mt = 0; mt < 2; mt++)
#pragma unroll
                for (int q = 0; q < 4; q++)
#pragma unroll
                    for (int s = 0; s < 2; s++)
                        mma_bf16(acc[mt][2 * q + s], ah[mt], &bh[q][2 * s]);
#pragma unroll
            for (int mt = 0; mt < 2; mt++)
#pragma unroll
                for (int q = 0; q < 4; q++)
#pragma unroll
                    for (int s = 0; s < 2; s++)
                        mma_bf16(acc[mt][2 * q + s], ah[mt], &bl[q][2 * s]);
#pragma unroll
            for (int mt = 0; mt < 2; mt++)
#pragma unroll
                for (int q = 0; q < 4; q++)
#pragma unroll
                    for (int s = 0; s < 2; s++)
                        mma_bf16(acc[mt][2 * q + s], al[mt], &bh[q][2 * s]);
        }
        if (c + 1 < nc) CP_WAIT0();
        __syncthreads();
    }

    // ---------------- epilogue ----------------
    const int g = lane >> 2, tg = lane & 3;
#pragma unroll
    for (int mt = 0; mt < 2; mt++) {
        const int m0 = mtile + wm * 32 + mt * 16 + g;
#pragma unroll
        for (int n8 = 0; n8 < 8; n8++) {
            const int nl = wn * 64 + n8 * 8 + tg * 2;
            const int n = ntile + nl;
            const float b0 = bias_s[nl], b1 = bias_s[nl + 1];
            float x0 = (acc[mt][n8][0] + b0) * scale;
            float x1 = (acc[mt][n8][1] + b1) * scale;
            float y0 = (acc[mt][n8][2] + b0) * scale;
            float y1 = (acc[mt][n8][3] + b1) * scale;
            if (ELU_) {
                x0 = x0 > 0.f ? x0 : expm1f(x0);
                x1 = x1 > 0.f ? x1 : expm1f(x1);
                y0 = y0 > 0.f ? y0 : expm1f(y0);
                y1 = y1 > 0.f ? y1 : expm1f(y1);
            }
            if (WF32) {
                *(float2*)(Cf + (size_t)m0 * ldcf + n) = make_float2(x0, x1);
                *(float2*)(Cf + (size_t)(m0 + 8) * ldcf + n) = make_float2(y0, y1);
            }
            if (WBF16) {
                union { bf16 h[2]; uint32_t u; } p;
                bf16 h0, h1;
                // row m0
                h0 = __float2bfloat16_rn(x0); h1 = __float2bfloat16_rn(x1);
                p.h[0] = h0; p.h[1] = h1;
                *(uint32_t*)(Chi + (size_t)m0 * ldcb + n) = p.u;
                p.h[0] = __float2bfloat16_rn(x0 - __bfloat162float(h0));
                p.h[1] = __float2bfloat16_rn(x1 - __bfloat162float(h1));
                *(uint32_t*)(Clo + (size_t)m0 * ldcb + n) = p.u;
                // row m0+8
                h0 = __float2bfloat16_rn(y0); h1 = __float2bfloat16_rn(y1);
                p.h[0] = h0; p.h[1] = h1;
                *(uint32_t*)(Chi + (size_t)(m0 + 8) * ldcb + n) = p.u;
                p.h[0] = __float2bfloat16_rn(y0 - __bfloat162float(h0));
                p.h[1] = __float2bfloat16_rn(y1 - __bfloat162float(h1));
                *(uint32_t*)(Clo + (size_t)(m0 + 8) * ldcb + n) = p.u;
            }
        }
    }
}

// ===========================================================================
// Attention: per-b block (4 warps, one per head). Outputs attn as bf16 hi/lo.
// ===========================================================================
__global__ void attention_kernel(const float* __restrict__ q,
                                 const float* __restrict__ k,
                                 const float* __restrict__ v,
                                 bf16* __restrict__ attn_hi,
                                 bf16* __restrict__ attn_lo,
                                 float* __restrict__ infl)
{
    const int b = blockIdx.x;
    const int tid = threadIdx.x;
    const int h = tid >> 5;
    const int lane = tid & 31;
    __shared__ float sw[H_][O_];

    const size_t base = (size_t)b * U_ + (size_t)h * HD_;
    const float4 qv = *(const float4*)(q + base + lane * 4);

    float s[O_];
#pragma unroll
    for (int o = 0; o < O_; o++) {
        const size_t kb = (size_t)o * B_ * U_ + base;
        const float4 kv = *(const float4*)(k + kb + lane * 4);
        float d = qv.x * kv.x + qv.y * kv.y + qv.z * kv.z + qv.w * kv.w;
#pragma unroll
        for (int off = 16; off > 0; off >>= 1)
            d += __shfl_xor_sync(0xffffffffu, d, off);
        s[o] = d;
    }
    const float m = fmaxf(s[0], fmaxf(s[1], s[2]));
    const float e0 = expf(s[0] - m), e1 = expf(s[1] - m), e2 = expf(s[2] - m);
    const float inv = 1.f / (e0 + e1 + e2);
    const float w[O_] = {e0 * inv, e1 * inv, e2 * inv};

    float4 a = make_float4(0.f, 0.f, 0.f, 0.f);
#pragma unroll
    for (int o = 0; o < O_; o++) {
        const size_t vb = (size_t)o * B_ * U_ + base;
        const float4 vv = *(const float4*)(v + vb + lane * 4);
        a.x = fmaf(w[o], vv.x, a.x);
        a.y = fmaf(w[o], vv.y, a.y);
        a.z = fmaf(w[o], vv.z, a.z);
        a.w = fmaf(w[o], vv.w, a.w);
    }
    {
        union { bf16 h[4]; uint2 u; } uh, ul;
        float xs[4] = {a.x, a.y, a.z, a.w};
#pragma unroll
        for (int t = 0; t < 4; t++) {
            bf16 hh = __float2bfloat16_rn(xs[t]);
            uh.h[t] = hh;
            ul.h[t] = __float2bfloat16_rn(xs[t] - __bfloat162float(hh));
        }
        *(uint2*)(attn_hi + base + lane * 4) = uh.u;
        *(uint2*)(attn_lo + base + lane * 4) = ul.u;
    }

    if (lane == 0) { sw[h][0] = w[0]; sw[h][1] = w[1]; sw[h][2] = w[2]; }
    __syncthreads();
    if (tid < O_)
        infl[(size_t)b * O_ + tid] =
            0.25f * (sw[0][tid] + sw[1][tid] + sw[2][tid] + sw[3][tid]);
}

// ===========================================================================
// Skinny heads (N in {1,6}) — fp32 SIMT
// ===========================================================================
__global__ void skinny_kernel(const float* __restrict__ A, int lda,
                              const float* __restrict__ W, int ldw,
                              const float* __restrict__ bias,
                              float* __restrict__ out, int ostride,
                              int M, int N, int K)
{
    const int idx = blockIdx.x * blockDim.x + threadIdx.x;
    if (idx >= M * N) return;
    const int b = idx / N;
    const int n = idx - b * N;
    const float4* a4 = (const float4*)(A + (size_t)b * lda);
    const float4* w4 = (const float4*)(W + (size_t)n * ldw);
    float acc = 0.f;
    const int K4 = K >> 2;
    for (int kk = 0; kk < K4; kk++) {
        const float4 av = a4[kk];
        const float4 wv = w4[kk];
        acc += av.x * wv.x + av.y * wv.y + av.z * wv.z + av.w * wv.w;
    }
    out[(size_t)b * ostride + n] = acc + bias[n];
}

// ===========================================================================
extern "C" void kernel_launch(void* const* d_in, const int* in_sizes, int n_in,
                              void* d_out, int out_size)
{
    const float* features = (const float*)d_in[0];
    const float* W_al = (const float*)d_in[1];
    const float* b_al = (const float*)d_in[2];
    const float* W_in = (const float*)d_in[3];
    const float* b_in = (const float*)d_in[4];
    const float* W_out = (const float*)d_in[5];
    const float* b_out = (const float*)d_in[6];
    const float* W_ah = (const float*)d_in[7];
    const float* b_ah = (const float*)d_in[8];
    const float* W_ap = (const float*)d_in[9];
    const float* b_ap = (const float*)d_in[10];
    const float* W_av = (const float*)d_in[11];
    const float* b_av = (const float*)d_in[12];
    const float* W_ol = (const float*)d_in[13];
    const float* b_ol = (const float*)d_in[14];
    const float* W_oh = (const float*)d_in[15];
    const float* b_oh = (const float*)d_in[16];
    const float* W_op = (const float*)d_in[17];
    const float* b_op = (const float*)d_in[18];
    const float* W_ov = (const float*)d_in[19];
    const float* b_ov = (const float*)d_in[20];
    float* out = (float*)d_out;

    bf16 *feat_hi, *feat_lo, *cat_hi, *cat_lo, *opp_hi, *opp_lo, *attn_hi, *attn_lo;
    bf16 *Wal_hi, *Wal_lo, *Win_hi, *Win_lo, *Wout_hi, *Wout_lo, *Wah_hi, *Wah_lo;
    bf16 *Wol_hi, *Wol_lo, *Woh_hi, *Woh_lo;
    float *q, *k, *v, *ah, *oh;
    cudaGetSymbolAddress((void**)&feat_hi, g_feat_hi);
    cudaGetSymbolAddress((void**)&feat_lo, g_feat_lo);
    cudaGetSymbolAddress((void**)&cat_hi, g_cat_hi);
    cudaGetSymbolAddress((void**)&cat_lo, g_cat_lo);
    cudaGetSymbolAddress((void**)&opp_hi, g_opp_hi);
    cudaGetSymbolAddress((void**)&opp_lo, g_opp_lo);
    cudaGetSymbolAddress((void**)&attn_hi, g_attn_hi);
    cudaGetSymbolAddress((void**)&attn_lo, g_attn_lo);
    cudaGetSymbolAddress((void**)&Wal_hi, g_Wal_hi);
    cudaGetSymbolAddress((void**)&Wal_lo, g_Wal_lo);
    cudaGetSymbolAddress((void**)&Win_hi, g_Win_hi);
    cudaGetSymbolAddress((void**)&Win_lo, g_Win_lo);
    cudaGetSymbolAddress((void**)&Wout_hi, g_Wout_hi);
    cudaGetSymbolAddress((void**)&Wout_lo, g_Wout_lo);
    cudaGetSymbolAddress((void**)&Wah_hi, g_Wah_hi);
    cudaGetSymbolAddress((void**)&Wah_lo, g_Wah_lo);
    cudaGetSymbolAddress((void**)&Wol_hi, g_Wol_hi);
    cudaGetSymbolAddress((void**)&Wol_lo, g_Wol_lo);
    cudaGetSymbolAddress((void**)&Woh_hi, g_Woh_hi);
    cudaGetSymbolAddress((void**)&Woh_lo, g_Woh_lo);
    cudaGetSymbolAddress((void**)&q, g_q);
    cudaGetSymbolAddress((void**)&k, g_k);
    cudaGetSymbolAddress((void**)&v, g_v);
    cudaGetSymbolAddress((void**)&ah, g_ah);
    cudaGetSymbolAddress((void**)&oh, g_oh);

    cudaFuncSetAttribute(gemm_mma<true, false, true>,
                         cudaFuncAttributeMaxDynamicSharedMemorySize, GEMM_SMEM);
    cudaFuncSetAttribute(gemm_mma<false, true, false>,
                         cudaFuncAttributeMaxDynamicSharedMemorySize, GEMM_SMEM);
    cudaFuncSetAttribute(gemm_mma<false, false, true>,
                         cudaFuncAttributeMaxDynamicSharedMemorySize, GEMM_SMEM);
    cudaFuncSetAttribute(gemm_mma<true, true, false>,
                         cudaFuncAttributeMaxDynamicSharedMemorySize, GEMM_SMEM);

    const size_t BU = (size_t)B_ * U_;
    const float qscale = 0.08838834764831845f;  // 1/sqrt(128)

    float* out_agent_policy = out;
    float* out_agent_value  = out + (size_t)B_ * A_;
    float* out_opp_policy   = out_agent_value + B_;
    float* out_opp_value    = out_opp_policy + (size_t)B_ * O_ * A_;
    float* out_infl         = out_opp_value + (size_t)B_ * O_;

    auto conv = [](const float* s, bf16* h, bf16* l, size_t n) {
        int n4 = (int)(n / 4);
        convert_split<<<(n4 + 255) / 256, 256>>>(s, h, l, n4);
    };
    conv(features, feat_hi, feat_lo, (size_t)B_ * F_);
    conv(W_al, Wal_hi, Wal_lo, (size_t)U_ * F_);
    conv(W_in, Win_hi, Win_lo, (size_t)3 * U_ * U_);
    conv(W_out, Wout_hi, Wout_lo, (size_t)U_ * U_);
    conv(W_ah, Wah_hi, Wah_lo, (size_t)U_ * 2 * U_);
    conv(W_ol, Wol_hi, Wol_lo, (size_t)O_ * U_ * F_);
    conv(W_oh, Woh_hi, Woh_lo, (size_t)O_ * U_ * U_);

    const dim3 gg(U_ / NT, B_ / MT);   // (4, 64)
    const dim3 gb(256);

    // 1) agent_latent -> cat[:, :U] (bf16 pair)
    gemm_mma<true, false, true><<<gg, gb, GEMM_SMEM>>>(
        feat_hi, feat_lo, F_, Wal_hi, Wal_lo, F_, b_al, 1.f,
        nullptr, 0, cat_hi, cat_lo, 2 * U_, F_);
    // 2) opp_lat[o] (bf16 pair)
    for (int o = 0; o < O_; o++)
        gemm_mma<true, false, true><<<gg, gb, GEMM_SMEM>>>(
            feat_hi, feat_lo, F_,
            Wol_hi + (size_t)o * U_ * F_, Wol_lo + (size_t)o * U_ * F_, F_,
            b_ol + o * U_, 1.f, nullptr, 0,
            opp_hi + o * BU, opp_lo + o * BU, U_, F_);
    // 3) q (fp32, pre-scaled)
    gemm_mma<false, true, false><<<gg, gb, GEMM_SMEM>>>(
        cat_hi, cat_lo, 2 * U_, Win_hi, Win_lo, U_, b_in, qscale,
        q, U_, nullptr, nullptr, 0, U_);
    // 4) k[o], v[o] (fp32)
    for (int o = 0; o < O_; o++)
        gemm_mma<false, true, false><<<gg, gb, GEMM_SMEM>>>(
            opp_hi + o * BU, opp_lo + o * BU, U_,
            Win_hi + (size_t)U_ * U_, Win_lo + (size_t)U_ * U_, U_,
            b_in + U_, 1.f, k + o * BU, U_, nullptr, nullptr, 0, U_);
    for (int o = 0; o < O_; o++)
        gemm_mma<false, true, false><<<gg, gb, GEMM_SMEM>>>(
            opp_hi + o * BU, opp_lo + o * BU, U_,
            Win_hi + (size_t)2 * U_ * U_, Win_lo + (size_t)2 * U_ * U_, U_,
            b_in + 2 * U_, 1.f, v + o * BU, U_, nullptr, nullptr, 0, U_);
    // 5) attention -> attn bf16 pair + influences
    attention_kernel<<<B_, 128>>>(q, k, v, attn_hi, attn_lo, out_infl);
    // 6) attn_out -> cat[:, U:] (bf16 pair)
    gemm_mma<false, false, true><<<gg, gb, GEMM_SMEM>>>(
        attn_hi, attn_lo, U_, Wout_hi, Wout_lo, U_, b_out, 1.f,
        nullptr, 0, cat_hi + U_, cat_lo + U_, 2 * U_, U_);
    // 7) agent_head (fp32)
    gemm_mma<true, true, false><<<gg, gb, GEMM_SMEM>>>(
        cat_hi, cat_lo, 2 * U_, Wah_hi, Wah_lo, 2 * U_, b_ah, 1.f,
        ah, U_, nullptr, nullptr, 0, 2 * U_);
    // 8) agent policy / value
    skinny_kernel<<<(B_ * A_ + 255) / 256, 256>>>(ah, U_, W_ap, U_, b_ap,
                                                  out_agent_policy, A_, B_, A_, U_);
    skinny_kernel<<<(B_ + 255) / 256, 256>>>(ah, U_, W_av, U_, b_av,
                                             out_agent_value, 1, B_, 1, U_);
    // 9) opp_heads[o] (fp32)
    for (int o = 0; o < O_; o++)
        gemm_mma<true, true, false><<<gg, gb, GEMM_SMEM>>>(
            opp_hi + o * BU, opp_lo + o * BU, U_,
            Woh_hi + (size_t)o * U_ * U_, Woh_lo + (size_t)o * U_ * U_, U_,
            b_oh + o * U_, 1.f, oh + o * BU, U_, nullptr, nullptr, 0, U_);
    // 10) opponent policies / values
    for (int o = 0; o < O_; o++) {
        skinny_kernel<<<(B_ * A_ + 255) / 256, 256>>>(
            oh + o * BU, U_, W_op + (size_t)o * A_ * U_, U_,
            b_op + o * A_, out_opp_policy + o * A_, O_ * A_, B_, A_, U_);
        skinny_kernel<<<(B_ + 255) / 256, 256>>>(
            oh + o * BU, U_, W_ov + (size_t)o * U_, U_,
            b_ov + o, out_opp_value + o, O_, B_, 1, U_);
    }
}

// round 4
// speedup vs baseline: 4.1256x; 1.9643x over previous
#include <cuda_runtime.h>
#include <cuda_fp16.h>
#include <math.h>
#include <stdint.h>

// Problem constants
#define B_ 8192
#define F_ 1024
#define U_ 512
#define O_ 3
#define A_ 6
#define H_ 4
#define HD_ 128

typedef __half h16;

// ===========================================================================
// Scratch (device globals)
// ===========================================================================
__device__ __align__(128) h16   g_feat_hi[(size_t)B_ * F_], g_feat_lo[(size_t)B_ * F_];
__device__ __align__(128) h16   g_cat_hi[(size_t)B_ * 2 * U_], g_cat_lo[(size_t)B_ * 2 * U_];
__device__ __align__(128) h16   g_opp_hi[(size_t)O_ * B_ * U_], g_opp_lo[(size_t)O_ * B_ * U_];
__device__ __align__(128) h16   g_attn_hi[(size_t)B_ * U_], g_attn_lo[(size_t)B_ * U_];
__device__ __align__(128) float g_q[(size_t)B_ * U_];
__device__ __align__(128) float g_kv[(size_t)O_ * B_ * 2 * U_];   // [O][B][k(512)|v(512)]
__device__ __align__(128) float g_ah[(size_t)B_ * U_];
__device__ __align__(128) float g_oh[(size_t)O_ * B_ * U_];
// weights (single fp16)
__device__ __align__(128) h16 g_Wal[(size_t)U_ * F_];
__device__ __align__(128) h16 g_Win[(size_t)3 * U_ * U_];
__device__ __align__(128) h16 g_Wout[(size_t)U_ * U_];
__device__ __align__(128) h16 g_Wah[(size_t)U_ * 2 * U_];
__device__ __align__(128) h16 g_Wol[(size_t)O_ * U_ * F_];
__device__ __align__(128) h16 g_Woh[(size_t)O_ * U_ * U_];

// ===========================================================================
// PTX helpers
// ===========================================================================
__device__ __forceinline__ uint32_t smem_u32(const void* p) {
    uint32_t a;
    asm("{ .reg .u64 t; cvta.to.shared.u64 t, %1; cvt.u32.u64 %0, t; }"
        : "=r"(a) : "l"(p));
    return a;
}
__device__ __forceinline__ void cp16(uint32_t s, const void* g) {
    asm volatile("cp.async.cg.shared.global [%0], [%1], 16;" :: "r"(s), "l"(g));
}
#define CP_COMMIT() asm volatile("cp.async.commit_group;" ::: "memory")
#define CP_WAIT0()  asm volatile("cp.async.wait_group 0;" ::: "memory")

__device__ __forceinline__ void ldsm4(uint32_t* r, uint32_t addr) {
    asm volatile("ldmatrix.sync.aligned.m8n8.x4.shared.b16 {%0,%1,%2,%3}, [%4];"
                 : "=r"(r[0]), "=r"(r[1]), "=r"(r[2]), "=r"(r[3]) : "r"(addr));
}
__device__ __forceinline__ void mma_f16(float* c, const uint32_t* a, const uint32_t* b) {
    asm volatile("mma.sync.aligned.m16n8k16.row.col.f32.f16.f16.f32 "
                 "{%0,%1,%2,%3}, {%4,%5,%6,%7}, {%8,%9}, {%0,%1,%2,%3};"
                 : "+f"(c[0]), "+f"(c[1]), "+f"(c[2]), "+f"(c[3])
                 : "r"(a[0]), "r"(a[1]), "r"(a[2]), "r"(a[3]),
                   "r"(b[0]), "r"(b[1]));
}

// ===========================================================================
// converts
// ===========================================================================
__global__ void convert_split_h(const float* __restrict__ src,
                                h16* __restrict__ hi, h16* __restrict__ lo, int n4)
{
    int i = blockIdx.x * blockDim.x + threadIdx.x;
    if (i >= n4) return;
    float4 x = ((const float4*)src)[i];
    h16 h[4], l[4];
    float xs[4] = {x.x, x.y, x.z, x.w};
#pragma unroll
    for (int j = 0; j < 4; j++) {
        h[j] = __float2half_rn(xs[j]);
        l[j] = __float2half_rn(xs[j] - __half2float(h[j]));
    }
    ((uint2*)hi)[i] = *(uint2*)h;
    ((uint2*)lo)[i] = *(uint2*)l;
}
__global__ void convert_w(const float* __restrict__ src, h16* __restrict__ w, int n4)
{
    int i = blockIdx.x * blockDim.x + threadIdx.x;
    if (i >= n4) return;
    float4 x = ((const float4*)src)[i];
    h16 h[4] = {__float2half_rn(x.x), __float2half_rn(x.y),
                __float2half_rn(x.z), __float2half_rn(x.w)};
    ((uint2*)w)[i] = *(uint2*)h;
}

// ===========================================================================
// 2-pass fp16 HMMA GEMM: C = act(((Ah+Al) @ W^T + bias) * scale)
// CTA 128x128, 8 warps (4Mx2N, warp 32x64), K stage 32, double buffer.
// z-batched via blockIdx.z strides.
// ===========================================================================
#define MT 128
#define NT 128
#define KB 32
#define RSTRIDE 80
#define COMP_BYTES (128 * RSTRIDE)       // 10240
#define OFF_AH 0
#define OFF_AL COMP_BYTES
#define OFF_W  (2 * COMP_BYTES)
#define STG_BYTES (3 * COMP_BYTES)       // 30720
#define GEMM_SMEM (1024 + 2 * STG_BYTES) // 62464

__device__ __forceinline__ void load_stage_async(
    uint32_t st, int tid,
    const h16* __restrict__ Ah, const h16* __restrict__ Al, int lda, int mtile,
    const h16* __restrict__ W, int ldw, int ntile, int k0)
{
#pragma unroll
    for (int i = 0; i < 2; i++) {
        int idx = tid + i * 256;        // 0..511
        int r = idx >> 2, c = idx & 3;
        uint32_t so = (uint32_t)(r * RSTRIDE + c * 16);
        size_t ga = (size_t)(mtile + r) * lda + k0 + c * 8;
        size_t gw = (size_t)(ntile + r) * ldw + k0 + c * 8;
        cp16(st + OFF_AH + so, Ah + ga);
        cp16(st + OFF_AL + so, Al + ga);
        cp16(st + OFF_W  + so, W + gw);
    }
    CP_COMMIT();
}

template <bool ELU_, bool WF32, bool WH16>
__global__ void __launch_bounds__(256)
gemm_mma(const h16* __restrict__ Ah, const h16* __restrict__ Al, int lda,
         unsigned long long Az,
         const h16* __restrict__ W, int ldw, unsigned long long Wz,
         const float* __restrict__ bias, int bz, float scale,
         float* __restrict__ Cf, int ldcf, unsigned long long Cfz,
         h16* __restrict__ Chi, h16* __restrict__ Clo, int ldcb,
         unsigned long long Cbz,
         int K)
{
    extern __shared__ __align__(128) char smem[];
    const int z = blockIdx.z;
    Ah += (size_t)z * Az;  Al += (size_t)z * Az;
    W  += (size_t)z * Wz;  bias += (size_t)z * bz;
    if (WF32) Cf += (size_t)z * Cfz;
    if (WH16) { Chi += (size_t)z * Cbz; Clo += (size_t)z * Cbz; }

    float* bias_s = (float*)smem;
    const uint32_t st0 = smem_u32(smem + 1024);
    const uint32_t st1 = st0 + STG_BYTES;

    const int tid = threadIdx.x, lane = tid & 31, wid = tid >> 5;
    const int wm = wid & 3, wn = wid >> 2;
    const int mtile = blockIdx.y * MT;
    const int ntile = blockIdx.x * NT;

    if (tid < NT) bias_s[tid] = bias[ntile + tid];

    float acc[2][8][4];
#pragma unroll
    for (int i = 0; i < 2; i++)
#pragma unroll
        for (int j = 0; j < 8; j++)
#pragma unroll
            for (int t = 0; t < 4; t++) acc[i][j][t] = 0.f;

    const int nc = K / KB;

    load_stage_async(st0, tid, Ah, Al, lda, mtile, W, ldw, ntile, 0);
    CP_WAIT0();
    __syncthreads();

    const uint32_t a_row = (uint32_t)(lane & 15);
    const uint32_t a_koff = (uint32_t)((lane >> 4) * 16);
    const uint32_t b_row = (uint32_t)(((lane >> 4) * 8) + (lane & 7));
    const uint32_t b_koff = (uint32_t)(((lane >> 3) & 1) * 16);

    for (int c = 0; c < nc; ++c) {
        const uint32_t cur = (c & 1) ? st1 : st0;
        if (c + 1 < nc)
            load_stage_async((c & 1) ? st0 : st1, tid,
                             Ah, Al, lda, mtile, W, ldw, ntile, (c + 1) * KB);
#pragma unroll
        for (int kc = 0; kc < 2; kc++) {
            uint32_t ah[2][4], al[2][4], wf[4][4];
#pragma unroll
            for (int mt = 0; mt < 2; mt++) {
                uint32_t row = wm * 32 + mt * 16 + a_row;
                uint32_t off = row * RSTRIDE + kc * 32 + a_koff;
                ldsm4(ah[mt], cur + OFF_AH + off);
                ldsm4(al[mt], cur + OFF_AL + off);
            }
#pragma unroll
            for (int q = 0; q < 4; q++) {
                uint32_t row = wn * 64 + q * 16 + b_row;
                uint32_t off = row * RSTRIDE + kc * 32 + b_koff;
                ldsm4(wf[q], cur + OFF_W + off);
            }
#pragma unroll
            for (int mt = 0; mt < 2; mt++)
#pragma unroll
                for (int q = 0; q < 4; q++)
#pragma unroll
                    for (int s = 0; s < 2; s++)
                        mma_f16(acc[mt][2 * q + s], ah[mt], &wf[q][2 * s]);
#pragma unroll
            for (int mt = 0; mt < 2; mt++)
#pragma unroll
                for (int q = 0; q < 4; q++)
#pragma unroll
                    for (int s = 0; s < 2; s++)
                        mma_f16(acc[mt][2 * q + s], al[mt], &wf[q][2 * s]);
        }
        if (c + 1 < nc) CP_WAIT0();
        __syncthreads();
    }

    // ---------------- epilogue ----------------
    const int g = lane >> 2, tg = lane & 3;
#pragma unroll
    for (int mt = 0; mt < 2; mt++) {
        const int m0 = mtile + wm * 32 + mt * 16 + g;
#pragma unroll
        for (int n8 = 0; n8 < 8; n8++) {
            const int nl = wn * 64 + n8 * 8 + tg * 2;
            const int n = ntile + nl;
            const float b0 = bias_s[nl], b1 = bias_s[nl + 1];
            float x0 = (acc[mt][n8][0] + b0) * scale;
            float x1 = (acc[mt][n8][1] + b1) * scale;
            float y0 = (acc[mt][n8][2] + b0) * scale;
            float y1 = (acc[mt][n8][3] + b1) * scale;
            if (ELU_) {
                x0 = x0 > 0.f ? x0 : expm1f(x0);
                x1 = x1 > 0.f ? x1 : expm1f(x1);
                y0 = y0 > 0.f ? y0 : expm1f(y0);
                y1 = y1 > 0.f ? y1 : expm1f(y1);
            }
            if (WF32) {
                *(float2*)(Cf + (size_t)m0 * ldcf + n) = make_float2(x0, x1);
                *(float2*)(Cf + (size_t)(m0 + 8) * ldcf + n) = make_float2(y0, y1);
            }
            if (WH16) {
                union { h16 h[2]; uint32_t u; } p;
                h16 h0, h1;
                h0 = __float2half_rn(x0); h1 = __float2half_rn(x1);
                p.h[0] = h0; p.h[1] = h1;
                *(uint32_t*)(Chi + (size_t)m0 * ldcb + n) = p.u;
                p.h[0] = __float2half_rn(x0 - __half2float(h0));
                p.h[1] = __float2half_rn(x1 - __half2float(h1));
                *(uint32_t*)(Clo + (size_t)m0 * ldcb + n) = p.u;
                h0 = __float2half_rn(y0); h1 = __float2half_rn(y1);
                p.h[0] = h0; p.h[1] = h1;
                *(uint32_t*)(Chi + (size_t)(m0 + 8) * ldcb + n) = p.u;
                p.h[0] = __float2half_rn(y0 - __half2float(h0));
                p.h[1] = __float2half_rn(y1 - __half2float(h1));
                *(uint32_t*)(Clo + (size_t)(m0 + 8) * ldcb + n) = p.u;
            }
        }
    }
}

// ===========================================================================
// Attention (kv fused layout [O][B][1024])
// ===========================================================================
__global__ void attention_kernel(const float* __restrict__ q,
                                 const float* __restrict__ kv,
                                 h16* __restrict__ attn_hi,
                                 h16* __restrict__ attn_lo,
                                 float* __restrict__ infl)
{
    const int b = blockIdx.x;
    const int tid = threadIdx.x;
    const int h = tid >> 5;
    const int lane = tid & 31;
    __shared__ float sw[H_][O_];

    const size_t base = (size_t)b * U_ + (size_t)h * HD_;
    const float4 qv = *(const float4*)(q + base + lane * 4);

    float s[O_];
#pragma unroll
    for (int o = 0; o < O_; o++) {
        const size_t kb = ((size_t)o * B_ + b) * (2 * U_) + (size_t)h * HD_;
        const float4 kvv = *(const float4*)(kv + kb + lane * 4);
        float d = qv.x * kvv.x + qv.y * kvv.y + qv.z * kvv.z + qv.w * kvv.w;
#pragma unroll
        for (int off = 16; off > 0; off >>= 1)
            d += __shfl_xor_sync(0xffffffffu, d, off);
        s[o] = d;
    }
    const float m = fmaxf(s[0], fmaxf(s[1], s[2]));
    const float e0 = expf(s[0] - m), e1 = expf(s[1] - m), e2 = expf(s[2] - m);
    const float inv = 1.f / (e0 + e1 + e2);
    const float w[O_] = {e0 * inv, e1 * inv, e2 * inv};

    float4 a = make_float4(0.f, 0.f, 0.f, 0.f);
#pragma unroll
    for (int o = 0; o < O_; o++) {
        const size_t vb = ((size_t)o * B_ + b) * (2 * U_) + U_ + (size_t)h * HD_;
        const float4 vv = *(const float4*)(kv + vb + lane * 4);
        a.x = fmaf(w[o], vv.x, a.x);
        a.y = fmaf(w[o], vv.y, a.y);
        a.z = fmaf(w[o], vv.z, a.z);
        a.w = fmaf(w[o], vv.w, a.w);
    }
    {
        union { h16 h[4]; uint2 u; } uh, ul;
        float xs[4] = {a.x, a.y, a.z, a.w};
#pragma unroll
        for (int t = 0; t < 4; t++) {
            h16 hh = __float2half_rn(xs[t]);
            uh.h[t] = hh;
            ul.h[t] = __float2half_rn(xs[t] - __half2float(hh));
        }
        *(uint2*)(attn_hi + base + lane * 4) = uh.u;
        *(uint2*)(attn_lo + base + lane * 4) = ul.u;
    }

    if (lane == 0) { sw[h][0] = w[0]; sw[h][1] = w[1]; sw[h][2] = w[2]; }
    __syncthreads();
    if (tid < O_)
        infl[(size_t)b * O_ + tid] =
            0.25f * (sw[0][tid] + sw[1][tid] + sw[2][tid] + sw[3][tid]);
}

// ===========================================================================
// Fused skinny heads — one warp per row, reads activation once
// ===========================================================================
__global__ void skinny_agent(const float* __restrict__ ah,
                             const float* __restrict__ Wp, const float* __restrict__ bp,
                             const float* __restrict__ Wv, const float* __restrict__ bv,
                             float* __restrict__ pol, float* __restrict__ val)
{
    const int wid = threadIdx.x >> 5, lane = threadIdx.x & 31;
    const int b = blockIdx.x * 8 + wid;
    const float4* x4 = (const float4*)(ah + (size_t)b * U_);
    float4 x[4];
#pragma unroll
    for (int j = 0; j < 4; j++) x[j] = x4[lane + 32 * j];
#pragma unroll
    for (int n = 0; n < 7; n++) {
        const float4* w4 = (const float4*)((n < 6) ? (Wp + (size_t)n * U_) : Wv);
        float d = 0.f;
#pragma unroll
        for (int j = 0; j < 4; j++) {
            float4 wv4 = w4[lane + 32 * j];
            d += x[j].x * wv4.x + x[j].y * wv4.y + x[j].z * wv4.z + x[j].w * wv4.w;
        }
#pragma unroll
        for (int off = 16; off > 0; off >>= 1) d += __shfl_xor_sync(~0u, d, off);
        if (lane == 0) {
            if (n < 6) pol[(size_t)b * A_ + n] = d + bp[n];
            else       val[b] = d + bv[0];
        }
    }
}

__global__ void skinny_opp(const float* __restrict__ oh,
                           const float* __restrict__ W_op, const float* __restrict__ b_op,
                           const float* __restrict__ W_ov, const float* __restrict__ b_ov,
                           float* __restrict__ pol, float* __restrict__ val)
{
    const int wid = threadIdx.x >> 5, lane = threadIdx.x & 31;
    const int b = blockIdx.x * 8 + wid;
    const int o = blockIdx.y;
    const float4* x4 = (const float4*)(oh + ((size_t)o * B_ + b) * U_);
    float4 x[4];
#pragma unroll
    for (int j = 0; j < 4; j++) x[j] = x4[lane + 32 * j];
    const float* Wp = W_op + (size_t)o * A_ * U_;
    const float* Wv = W_ov + (size_t)o * U_;
#pragma unroll
    for (int n = 0; n < 7; n++) {
        const float4* w4 = (const float4*)((n < 6) ? (Wp + (size_t)n * U_) : Wv);
        float d = 0.f;
#pragma unroll
        for (int j = 0; j < 4; j++) {
            float4 wv4 = w4[lane + 32 * j];
            d += x[j].x * wv4.x + x[j].y * wv4.y + x[j].z * wv4.z + x[j].w * wv4.w;
        }
#pragma unroll
        for (int off = 16; off > 0; off >>= 1) d += __shfl_xor_sync(~0u, d, off);
        if (lane == 0) {
            if (n < 6) pol[(size_t)b * (O_ * A_) + o * A_ + n] = d + b_op[o * A_ + n];
            else       val[(size_t)b * O_ + o] = d + b_ov[o];
        }
    }
}

// ===========================================================================
extern "C" void kernel_launch(void* const* d_in, const int* in_sizes, int n_in,
                              void* d_out, int out_size)
{
    const float* features = (const float*)d_in[0];
    const float* W_al = (const float*)d_in[1];
    const float* b_al = (const float*)d_in[2];
    const float* W_in = (const float*)d_in[3];
    const float* b_in = (const float*)d_in[4];
    const float* W_out = (const float*)d_in[5];
    const float* b_out = (const float*)d_in[6];
    const float* W_ah = (const float*)d_in[7];
    const float* b_ah = (const float*)d_in[8];
    const float* W_ap = (const float*)d_in[9];
    const float* b_ap = (const float*)d_in[10];
    const float* W_av = (const float*)d_in[11];
    const float* b_av = (const float*)d_in[12];
    const float* W_ol = (const float*)d_in[13];
    const float* b_ol = (const float*)d_in[14];
    const float* W_oh = (const float*)d_in[15];
    const float* b_oh = (const float*)d_in[16];
    const float* W_op = (const float*)d_in[17];
    const float* b_op = (const float*)d_in[18];
    const float* W_ov = (const float*)d_in[19];
    const float* b_ov = (const float*)d_in[20];
    float* out = (float*)d_out;

    h16 *feat_hi, *feat_lo, *cat_hi, *cat_lo, *opp_hi, *opp_lo, *attn_hi, *attn_lo;
    h16 *Wal, *Win, *Wout, *Wah, *Wol, *Woh;
    float *q, *kv, *ah, *oh;
    cudaGetSymbolAddress((void**)&feat_hi, g_feat_hi);
    cudaGetSymbolAddress((void**)&feat_lo, g_feat_lo);
    cudaGetSymbolAddress((void**)&cat_hi, g_cat_hi);
    cudaGetSymbolAddress((void**)&cat_lo, g_cat_lo);
    cudaGetSymbolAddress((void**)&opp_hi, g_opp_hi);
    cudaGetSymbolAddress((void**)&opp_lo, g_opp_lo);
    cudaGetSymbolAddress((void**)&attn_hi, g_attn_hi);
    cudaGetSymbolAddress((void**)&attn_lo, g_attn_lo);
    cudaGetSymbolAddress((void**)&Wal, g_Wal);
    cudaGetSymbolAddress((void**)&Win, g_Win);
    cudaGetSymbolAddress((void**)&Wout, g_Wout);
    cudaGetSymbolAddress((void**)&Wah, g_Wah);
    cudaGetSymbolAddress((void**)&Wol, g_Wol);
    cudaGetSymbolAddress((void**)&Woh, g_Woh);
    cudaGetSymbolAddress((void**)&q, g_q);
    cudaGetSymbolAddress((void**)&kv, g_kv);
    cudaGetSymbolAddress((void**)&ah, g_ah);
    cudaGetSymbolAddress((void**)&oh, g_oh);

    cudaFuncSetAttribute(gemm_mma<true, false, true>,
                         cudaFuncAttributeMaxDynamicSharedMemorySize, GEMM_SMEM);
    cudaFuncSetAttribute(gemm_mma<false, true, false>,
                         cudaFuncAttributeMaxDynamicSharedMemorySize, GEMM_SMEM);
    cudaFuncSetAttribute(gemm_mma<false, false, true>,
                         cudaFuncAttributeMaxDynamicSharedMemorySize, GEMM_SMEM);
    cudaFuncSetAttribute(gemm_mma<true, true, false>,
                         cudaFuncAttributeMaxDynamicSharedMemorySize, GEMM_SMEM);

    const size_t BU = (size_t)B_ * U_;
    const float qscale = 0.08838834764831845f;  // 1/sqrt(128)

    float* out_agent_policy = out;
    float* out_agent_value  = out + (size_t)B_ * A_;
    float* out_opp_policy   = out_agent_value + B_;
    float* out_opp_value    = out_opp_policy + (size_t)B_ * O_ * A_;
    float* out_infl         = out_opp_value + (size_t)B_ * O_;

    // converts
    {
        int n4 = (int)((size_t)B_ * F_ / 4);
        convert_split_h<<<(n4 + 255) / 256, 256>>>(features, feat_hi, feat_lo, n4);
    }
    auto convw = [](const float* s, h16* w, size_t n) {
        int n4 = (int)(n / 4);
        convert_w<<<(n4 + 255) / 256, 256>>>(s, w, n4);
    };
    convw(W_al, Wal, (size_t)U_ * F_);
    convw(W_in, Win, (size_t)3 * U_ * U_);
    convw(W_out, Wout, (size_t)U_ * U_);
    convw(W_ah, Wah, (size_t)U_ * 2 * U_);
    convw(W_ol, Wol, (size_t)O_ * U_ * F_);
    convw(W_oh, Woh, (size_t)O_ * U_ * U_);

    const dim3 gb(256);

    // 1) agent_latent -> cat[:, :U]
    gemm_mma<true, false, true><<<dim3(4, 64, 1), gb, GEMM_SMEM>>>(
        feat_hi, feat_lo, F_, 0ull, Wal, F_, 0ull, b_al, 0, 1.f,
        nullptr, 0, 0ull, cat_hi, cat_lo, 2 * U_, 0ull, F_);
    // 2) opp_lat (z=3)
    gemm_mma<true, false, true><<<dim3(4, 64, 3), gb, GEMM_SMEM>>>(
        feat_hi, feat_lo, F_, 0ull,
        Wol, F_, (unsigned long long)U_ * F_, b_ol, U_, 1.f,
        nullptr, 0, 0ull, opp_hi, opp_lo, U_, (unsigned long long)BU, F_);
    // 3) q (pre-scaled)
    gemm_mma<false, true, false><<<dim3(4, 64, 1), gb, GEMM_SMEM>>>(
        cat_hi, cat_lo, 2 * U_, 0ull, Win, U_, 0ull, b_in, 0, qscale,
        q, U_, 0ull, nullptr, nullptr, 0, 0ull, U_);
    // 4) k+v fused (N=1024), z=3 over opponents
    gemm_mma<false, true, false><<<dim3(8, 64, 3), gb, GEMM_SMEM>>>(
        opp_hi, opp_lo, U_, (unsigned long long)BU,
        Win + (size_t)U_ * U_, U_, 0ull, b_in + U_, 0, 1.f,
        kv, 2 * U_, (unsigned long long)B_ * 2 * U_,
        nullptr, nullptr, 0, 0ull, U_);
    // 5) attention
    attention_kernel<<<B_, 128>>>(q, kv, attn_hi, attn_lo, out_infl);
    // 6) attn_out -> cat[:, U:]
    gemm_mma<false, false, true><<<dim3(4, 64, 1), gb, GEMM_SMEM>>>(
        attn_hi, attn_lo, U_, 0ull, Wout, U_, 0ull, b_out, 0, 1.f,
        nullptr, 0, 0ull, cat_hi + U_, cat_lo + U_, 2 * U_, 0ull, U_);
    // 7) agent_head
    gemm_mma<true, true, false><<<dim3(4, 64, 1), gb, GEMM_SMEM>>>(
        cat_hi, cat_lo, 2 * U_, 0ull, Wah, 2 * U_, 0ull, b_ah, 0, 1.f,
        ah, U_, 0ull, nullptr, nullptr, 0, 0ull, 2 * U_);
    // 8) agent policy + value (fused)
    skinny_agent<<<B_ / 8, 256>>>(ah, W_ap, b_ap, W_av, b_av,
                                  out_agent_policy, out_agent_value);
    // 9) opp_heads (z=3)
    gemm_mma<true, true, false><<<dim3(4, 64, 3), gb, GEMM_SMEM>>>(
        opp_hi, opp_lo, U_, (unsigned long long)BU,
        Woh, U_, (unsigned long long)U_ * U_, b_oh, U_, 1.f,
        oh, U_, (unsigned long long)BU, nullptr, nullptr, 0, 0ull, U_);
    // 10) opponent policies + values (fused)
    skinny_opp<<<dim3(B_ / 8, 3), 256>>>(oh, W_op, b_op, W_ov, b_ov,
                                         out_opp_policy, out_opp_value);
}

// round 5
// speedup vs baseline: 4.2665x; 1.0342x over previous
#include <cuda_runtime.h>
#include <cuda_fp16.h>
#include <math.h>
#include <stdint.h>

// Problem constants
#define B_ 8192
#define F_ 1024
#define U_ 512
#define O_ 3
#define A_ 6
#define H_ 4
#define HD_ 128

typedef __half h16;

// ===========================================================================
// Scratch (device globals)
// ===========================================================================
__device__ __align__(128) h16   g_feat_hi[(size_t)B_ * F_], g_feat_lo[(size_t)B_ * F_];
__device__ __align__(128) h16   g_cat_hi[(size_t)B_ * 2 * U_], g_cat_lo[(size_t)B_ * 2 * U_];
__device__ __align__(128) h16   g_opp_hi[(size_t)O_ * B_ * U_], g_opp_lo[(size_t)O_ * B_ * U_];
__device__ __align__(128) h16   g_attn_hi[(size_t)B_ * U_], g_attn_lo[(size_t)B_ * U_];
__device__ __align__(128) float g_q[(size_t)B_ * U_];
__device__ __align__(128) float g_kv[(size_t)O_ * B_ * 2 * U_];   // [O][B][k(512)|v(512)]
__device__ __align__(128) float g_ah[(size_t)B_ * U_];
__device__ __align__(128) float g_oh[(size_t)O_ * B_ * U_];
// weights (single fp16)
__device__ __align__(128) h16 g_Wal[(size_t)U_ * F_];
__device__ __align__(128) h16 g_Win[(size_t)3 * U_ * U_];
__device__ __align__(128) h16 g_Wout[(size_t)U_ * U_];
__device__ __align__(128) h16 g_Wah[(size_t)U_ * 2 * U_];
__device__ __align__(128) h16 g_Wol[(size_t)O_ * U_ * F_];
__device__ __align__(128) h16 g_Woh[(size_t)O_ * U_ * U_];

// ===========================================================================
// PTX helpers
// ===========================================================================
__device__ __forceinline__ uint32_t smem_u32(const void* p) {
    uint32_t a;
    asm("{ .reg .u64 t; cvta.to.shared.u64 t, %1; cvt.u32.u64 %0, t; }"
        : "=r"(a) : "l"(p));
    return a;
}
__device__ __forceinline__ void cp16(uint32_t s, const void* g) {
    asm volatile("cp.async.cg.shared.global [%0], [%1], 16;" :: "r"(s), "l"(g));
}
#define CP_COMMIT() asm volatile("cp.async.commit_group;" ::: "memory")
#define CP_WAIT0()  asm volatile("cp.async.wait_group 0;" ::: "memory")
#define CP_WAIT1()  asm volatile("cp.async.wait_group 1;" ::: "memory")

__device__ __forceinline__ void ldsm4(uint32_t* r, uint32_t addr) {
    asm volatile("ldmatrix.sync.aligned.m8n8.x4.shared.b16 {%0,%1,%2,%3}, [%4];"
                 : "=r"(r[0]), "=r"(r[1]), "=r"(r[2]), "=r"(r[3]) : "r"(addr));
}
__device__ __forceinline__ void mma_f16(float* c, const uint32_t* a, const uint32_t* b) {
    asm volatile("mma.sync.aligned.m16n8k16.row.col.f32.f16.f16.f32 "
                 "{%0,%1,%2,%3}, {%4,%5,%6,%7}, {%8,%9}, {%0,%1,%2,%3};"
                 : "+f"(c[0]), "+f"(c[1]), "+f"(c[2]), "+f"(c[3])
                 : "r"(a[0]), "r"(a[1]), "r"(a[2]), "r"(a[3]),
                   "r"(b[0]), "r"(b[1]));
}

// ===========================================================================
// converts
// ===========================================================================
__global__ void convert_split_h(const float* __restrict__ src,
                                h16* __restrict__ hi, h16* __restrict__ lo, int n4)
{
    int i = blockIdx.x * blockDim.x + threadIdx.x;
    if (i >= n4) return;
    float4 x = ((const float4*)src)[i];
    h16 h[4], l[4];
    float xs[4] = {x.x, x.y, x.z, x.w};
#pragma unroll
    for (int j = 0; j < 4; j++) {
        h[j] = __float2half_rn(xs[j]);
        l[j] = __float2half_rn(xs[j] - __half2float(h[j]));
    }
    ((uint2*)hi)[i] = *(uint2*)h;
    ((uint2*)lo)[i] = *(uint2*)l;
}
__global__ void convert_w(const float* __restrict__ src, h16* __restrict__ w, int n4)
{
    int i = blockIdx.x * blockDim.x + threadIdx.x;
    if (i >= n4) return;
    float4 x = ((const float4*)src)[i];
    h16 h[4] = {__float2half_rn(x.x), __float2half_rn(x.y),
                __float2half_rn(x.z), __float2half_rn(x.w)};
    ((uint2*)w)[i] = *(uint2*)h;
}

// ===========================================================================
// 2-pass fp16 HMMA GEMM: C = act(((Ah+Al) @ W^T + bias) * scale)
// CTA 128x128, 8 warps (4Mx2N, warp 32x64), K stage 32.
// 3-stage cp.async ring (wait_group 1), occupancy 2.
// ===========================================================================
#define MT 128
#define NT 128
#define KB 32
#define RSTRIDE 80
#define COMP_BYTES (128 * RSTRIDE)       // 10240
#define OFF_AH 0
#define OFF_AL COMP_BYTES
#define OFF_W  (2 * COMP_BYTES)
#define STG_BYTES (3 * COMP_BYTES)       // 30720
#define NSTAGE 3
#define GEMM_SMEM (1024 + NSTAGE * STG_BYTES)   // 93184

__device__ __forceinline__ void load_stage_async(
    uint32_t st, int tid,
    const h16* __restrict__ Ah, const h16* __restrict__ Al, int lda, int mtile,
    const h16* __restrict__ W, int ldw, int ntile, int k0)
{
#pragma unroll
    for (int i = 0; i < 2; i++) {
        int idx = tid + i * 256;        // 0..511
        int r = idx >> 2, c = idx & 3;
        uint32_t so = (uint32_t)(r * RSTRIDE + c * 16);
        size_t ga = (size_t)(mtile + r) * lda + k0 + c * 8;
        size_t gw = (size_t)(ntile + r) * ldw + k0 + c * 8;
        cp16(st + OFF_AH + so, Ah + ga);
        cp16(st + OFF_AL + so, Al + ga);
        cp16(st + OFF_W  + so, W + gw);
    }
    CP_COMMIT();
}

template <bool ELU_, bool WF32, bool WH16>
__global__ void __launch_bounds__(256, 2)
gemm_mma(const h16* __restrict__ Ah, const h16* __restrict__ Al, int lda,
         unsigned long long Az,
         const h16* __restrict__ W, int ldw, unsigned long long Wz,
         const float* __restrict__ bias, int bz, float scale,
         float* __restrict__ Cf, int ldcf, unsigned long long Cfz,
         h16* __restrict__ Chi, h16* __restrict__ Clo, int ldcb,
         unsigned long long Cbz,
         int K)
{
    extern __shared__ __align__(128) char smem[];
    const int z = blockIdx.z;
    Ah += (size_t)z * Az;  Al += (size_t)z * Az;
    W  += (size_t)z * Wz;  bias += (size_t)z * bz;
    if (WF32) Cf += (size_t)z * Cfz;
    if (WH16) { Chi += (size_t)z * Cbz; Clo += (size_t)z * Cbz; }

    float* bias_s = (float*)smem;
    const uint32_t st0 = smem_u32(smem + 1024);

    const int tid = threadIdx.x, lane = tid & 31, wid = tid >> 5;
    const int wm = wid & 3, wn = wid >> 2;
    const int mtile = blockIdx.y * MT;
    const int ntile = blockIdx.x * NT;

    if (tid < NT) bias_s[tid] = bias[ntile + tid];

    float acc[2][8][4];
#pragma unroll
    for (int i = 0; i < 2; i++)
#pragma unroll
        for (int j = 0; j < 8; j++)
#pragma unroll
            for (int t = 0; t < 4; t++) acc[i][j][t] = 0.f;

    const int nc = K / KB;

    // prologue: 2 stages in flight
    load_stage_async(st0, tid, Ah, Al, lda, mtile, W, ldw, ntile, 0);
    if (nc > 1)
        load_stage_async(st0 + STG_BYTES, tid, Ah, Al, lda, mtile, W, ldw, ntile, KB);

    const uint32_t a_row = (uint32_t)(lane & 15);
    const uint32_t a_koff = (uint32_t)((lane >> 4) * 16);
    const uint32_t b_row = (uint32_t)(((lane >> 4) * 8) + (lane & 7));
    const uint32_t b_koff = (uint32_t)(((lane >> 3) & 1) * 16);

    int sidx = 0;            // stage index of chunk c
    for (int c = 0; c < nc; ++c) {
        if (c + 1 < nc) CP_WAIT1(); else CP_WAIT0();
        __syncthreads();
        if (c + 2 < nc) {
            int nidx = sidx + 2; if (nidx >= NSTAGE) nidx -= NSTAGE;
            load_stage_async(st0 + nidx * STG_BYTES, tid,
                             Ah, Al, lda, mtile, W, ldw, ntile, (c + 2) * KB);
        }
        const uint32_t cur = st0 + sidx * STG_BYTES;
#pragma unroll
        for (int kc = 0; kc < 2; kc++) {
            uint32_t ah[2][4], al[2][4], wf[4][4];
#pragma unroll
            for (int mt = 0; mt < 2; mt++) {
                uint32_t row = wm * 32 + mt * 16 + a_row;
                uint32_t off = row * RSTRIDE + kc * 32 + a_koff;
                ldsm4(ah[mt], cur + OFF_AH + off);
                ldsm4(al[mt], cur + OFF_AL + off);
            }
#pragma unroll
            for (int q = 0; q < 4; q++) {
                uint32_t row = wn * 64 + q * 16 + b_row;
                uint32_t off = row * RSTRIDE + kc * 32 + b_koff;
                ldsm4(wf[q], cur + OFF_W + off);
            }
#pragma unroll
            for (int mt = 0; mt < 2; mt++)
#pragma unroll
                for (int q = 0; q < 4; q++)
#pragma unroll
                    for (int s = 0; s < 2; s++)
                        mma_f16(acc[mt][2 * q + s], ah[mt], &wf[q][2 * s]);
#pragma unroll
            for (int mt = 0; mt < 2; mt++)
#pragma unroll
                for (int q = 0; q < 4; q++)
#pragma unroll
                    for (int s = 0; s < 2; s++)
                        mma_f16(acc[mt][2 * q + s], al[mt], &wf[q][2 * s]);
        }
        if (++sidx >= NSTAGE) sidx = 0;
    }

    // ---------------- epilogue ----------------
    const int g = lane >> 2, tg = lane & 3;
#pragma unroll
    for (int mt = 0; mt < 2; mt++) {
        const int m0 = mtile + wm * 32 + mt * 16 + g;
#pragma unroll
        for (int n8 = 0; n8 < 8; n8++) {
            const int nl = wn * 64 + n8 * 8 + tg * 2;
            const int n = ntile + nl;
            const float b0 = bias_s[nl], b1 = bias_s[nl + 1];
            float x0 = (acc[mt][n8][0] + b0) * scale;
            float x1 = (acc[mt][n8][1] + b1) * scale;
            float y0 = (acc[mt][n8][2] + b0) * scale;
            float y1 = (acc[mt][n8][3] + b1) * scale;
            if (ELU_) {
                x0 = x0 > 0.f ? x0 : expm1f(x0);
                x1 = x1 > 0.f ? x1 : expm1f(x1);
                y0 = y0 > 0.f ? y0 : expm1f(y0);
                y1 = y1 > 0.f ? y1 : expm1f(y1);
            }
            if (WF32) {
                *(float2*)(Cf + (size_t)m0 * ldcf + n) = make_float2(x0, x1);
                *(float2*)(Cf + (size_t)(m0 + 8) * ldcf + n) = make_float2(y0, y1);
            }
            if (WH16) {
                union { h16 h[2]; uint32_t u; } p;
                h16 h0, h1;
                h0 = __float2half_rn(x0); h1 = __float2half_rn(x1);
                p.h[0] = h0; p.h[1] = h1;
                *(uint32_t*)(Chi + (size_t)m0 * ldcb + n) = p.u;
                p.h[0] = __float2half_rn(x0 - __half2float(h0));
                p.h[1] = __float2half_rn(x1 - __half2float(h1));
                *(uint32_t*)(Clo + (size_t)m0 * ldcb + n) = p.u;
                h0 = __float2half_rn(y0); h1 = __float2half_rn(y1);
                p.h[0] = h0; p.h[1] = h1;
                *(uint32_t*)(Chi + (size_t)(m0 + 8) * ldcb + n) = p.u;
                p.h[0] = __float2half_rn(y0 - __half2float(h0));
                p.h[1] = __float2half_rn(y1 - __half2float(h1));
                *(uint32_t*)(Clo + (size_t)(m0 + 8) * ldcb + n) = p.u;
            }
        }
    }
}

// ===========================================================================
// Attention (kv fused layout [O][B][1024])
// ===========================================================================
__global__ void attention_kernel(const float* __restrict__ q,
                                 const float* __restrict__ kv,
                                 h16* __restrict__ attn_hi,
                                 h16* __restrict__ attn_lo,
                                 float* __restrict__ infl)
{
    const int b = blockIdx.x;
    const int tid = threadIdx.x;
    const int h = tid >> 5;
    const int lane = tid & 31;
    __shared__ float sw[H_][O_];

    const size_t base = (size_t)b * U_ + (size_t)h * HD_;
    const float4 qv = *(const float4*)(q + base + lane * 4);

    float s[O_];
#pragma unroll
    for (int o = 0; o < O_; o++) {
        const size_t kb = ((size_t)o * B_ + b) * (2 * U_) + (size_t)h * HD_;
        const float4 kvv = *(const float4*)(kv + kb + lane * 4);
        float d = qv.x * kvv.x + qv.y * kvv.y + qv.z * kvv.z + qv.w * kvv.w;
#pragma unroll
        for (int off = 16; off > 0; off >>= 1)
            d += __shfl_xor_sync(0xffffffffu, d, off);
        s[o] = d;
    }
    const float m = fmaxf(s[0], fmaxf(s[1], s[2]));
    const float e0 = expf(s[0] - m), e1 = expf(s[1] - m), e2 = expf(s[2] - m);
    const float inv = 1.f / (e0 + e1 + e2);
    const float w[O_] = {e0 * inv, e1 * inv, e2 * inv};

    float4 a = make_float4(0.f, 0.f, 0.f, 0.f);
#pragma unroll
    for (int o = 0; o < O_; o++) {
        const size_t vb = ((size_t)o * B_ + b) * (2 * U_) + U_ + (size_t)h * HD_;
        const float4 vv = *(const float4*)(kv + vb + lane * 4);
        a.x = fmaf(w[o], vv.x, a.x);
        a.y = fmaf(w[o], vv.y, a.y);
        a.z = fmaf(w[o], vv.z, a.z);
        a.w = fmaf(w[o], vv.w, a.w);
    }
    {
        union { h16 h[4]; uint2 u; } uh, ul;
        float xs[4] = {a.x, a.y, a.z, a.w};
#pragma unroll
        for (int t = 0; t < 4; t++) {
            h16 hh = __float2half_rn(xs[t]);
            uh.h[t] = hh;
            ul.h[t] = __float2half_rn(xs[t] - __half2float(hh));
        }
        *(uint2*)(attn_hi + base + lane * 4) = uh.u;
        *(uint2*)(attn_lo + base + lane * 4) = ul.u;
    }

    if (lane == 0) { sw[h][0] = w[0]; sw[h][1] = w[1]; sw[h][2] = w[2]; }
    __syncthreads();
    if (tid < O_)
        infl[(size_t)b * O_ + tid] =
            0.25f * (sw[0][tid] + sw[1][tid] + sw[2][tid] + sw[3][tid]);
}

// ===========================================================================
// Fused skinny heads — one warp per row
// ===========================================================================
__global__ void skinny_agent(const float* __restrict__ ah,
                             const float* __restrict__ Wp, const float* __restrict__ bp,
                             const float* __restrict__ Wv, const float* __restrict__ bv,
                             float* __restrict__ pol, float* __restrict__ val)
{
    const int wid = threadIdx.x >> 5, lane = threadIdx.x & 31;
    const int b = blockIdx.x * 8 + wid;
    const float4* x4 = (const float4*)(ah + (size_t)b * U_);
    float4 x[4];
#pragma unroll
    for (int j = 0; j < 4; j++) x[j] = x4[lane + 32 * j];
#pragma unroll
    for (int n = 0; n < 7; n++) {
        const float4* w4 = (const float4*)((n < 6) ? (Wp + (size_t)n * U_) : Wv);
        float d = 0.f;
#pragma unroll
        for (int j = 0; j < 4; j++) {
            float4 wv4 = w4[lane + 32 * j];
            d += x[j].x * wv4.x + x[j].y * wv4.y + x[j].z * wv4.z + x[j].w * wv4.w;
        }
#pragma unroll
        for (int off = 16; off > 0; off >>= 1) d += __shfl_xor_sync(~0u, d, off);
        if (lane == 0) {
            if (n < 6) pol[(size_t)b * A_ + n] = d + bp[n];
            else       val[b] = d + bv[0];
        }
    }
}

__global__ void skinny_opp(const float* __restrict__ oh,
                           const float* __restrict__ W_op, const float* __restrict__ b_op,
                           const float* __restrict__ W_ov, const float* __restrict__ b_ov,
                           float* __restrict__ pol, float* __restrict__ val)
{
    const int wid = threadIdx.x >> 5, lane = threadIdx.x & 31;
    const int b = blockIdx.x * 8 + wid;
    const int o = blockIdx.y;
    const float4* x4 = (const float4*)(oh + ((size_t)o * B_ + b) * U_);
    float4 x[4];
#pragma unroll
    for (int j = 0; j < 4; j++) x[j] = x4[lane + 32 * j];
    const float* Wp = W_op + (size_t)o * A_ * U_;
    const float* Wv = W_ov + (size_t)o * U_;
#pragma unroll
    for (int n = 0; n < 7; n++) {
        const float4* w4 = (const float4*)((n < 6) ? (Wp + (size_t)n * U_) : Wv);
        float d = 0.f;
#pragma unroll
        for (int j = 0; j < 4; j++) {
            float4 wv4 = w4[lane + 32 * j];
            d += x[j].x * wv4.x + x[j].y * wv4.y + x[j].z * wv4.z + x[j].w * wv4.w;
        }
#pragma unroll
        for (int off = 16; off > 0; off >>= 1) d += __shfl_xor_sync(~0u, d, off);
        if (lane == 0) {
            if (n < 6) pol[(size_t)b * (O_ * A_) + o * A_ + n] = d + b_op[o * A_ + n];
            else       val[(size_t)b * O_ + o] = d + b_ov[o];
        }
    }
}

// ===========================================================================
extern "C" void kernel_launch(void* const* d_in, const int* in_sizes, int n_in,
                              void* d_out, int out_size)
{
    const float* features = (const float*)d_in[0];
    const float* W_al = (const float*)d_in[1];
    const float* b_al = (const float*)d_in[2];
    const float* W_in = (const float*)d_in[3];
    const float* b_in = (const float*)d_in[4];
    const float* W_out = (const float*)d_in[5];
    const float* b_out = (const float*)d_in[6];
    const float* W_ah = (const float*)d_in[7];
    const float* b_ah = (const float*)d_in[8];
    const float* W_ap = (const float*)d_in[9];
    const float* b_ap = (const float*)d_in[10];
    const float* W_av = (const float*)d_in[11];
    const float* b_av = (const float*)d_in[12];
    const float* W_ol = (const float*)d_in[13];
    const float* b_ol = (const float*)d_in[14];
    const float* W_oh = (const float*)d_in[15];
    const float* b_oh = (const float*)d_in[16];
    const float* W_op = (const float*)d_in[17];
    const float* b_op = (const float*)d_in[18];
    const float* W_ov = (const float*)d_in[19];
    const float* b_ov = (const float*)d_in[20];
    float* out = (float*)d_out;

    h16 *feat_hi, *feat_lo, *cat_hi, *cat_lo, *opp_hi, *opp_lo, *attn_hi, *attn_lo;
    h16 *Wal, *Win, *Wout, *Wah, *Wol, *Woh;
    float *q, *kv, *ah, *oh;
    cudaGetSymbolAddress((void**)&feat_hi, g_feat_hi);
    cudaGetSymbolAddress((void**)&feat_lo, g_feat_lo);
    cudaGetSymbolAddress((void**)&cat_hi, g_cat_hi);
    cudaGetSymbolAddress((void**)&cat_lo, g_cat_lo);
    cudaGetSymbolAddress((void**)&opp_hi, g_opp_hi);
    cudaGetSymbolAddress((void**)&opp_lo, g_opp_lo);
    cudaGetSymbolAddress((void**)&attn_hi, g_attn_hi);
    cudaGetSymbolAddress((void**)&attn_lo, g_attn_lo);
    cudaGetSymbolAddress((void**)&Wal, g_Wal);
    cudaGetSymbolAddress((void**)&Win, g_Win);
    cudaGetSymbolAddress((void**)&Wout, g_Wout);
    cudaGetSymbolAddress((void**)&Wah, g_Wah);
    cudaGetSymbolAddress((void**)&Wol, g_Wol);
    cudaGetSymbolAddress((void**)&Woh, g_Woh);
    cudaGetSymbolAddress((void**)&q, g_q);
    cudaGetSymbolAddress((void**)&kv, g_kv);
    cudaGetSymbolAddress((void**)&ah, g_ah);
    cudaGetSymbolAddress((void**)&oh, g_oh);

    cudaFuncSetAttribute(gemm_mma<true, false, true>,
                         cudaFuncAttributeMaxDynamicSharedMemorySize, GEMM_SMEM);
    cudaFuncSetAttribute(gemm_mma<false, true, false>,
                         cudaFuncAttributeMaxDynamicSharedMemorySize, GEMM_SMEM);
    cudaFuncSetAttribute(gemm_mma<false, false, true>,
                         cudaFuncAttributeMaxDynamicSharedMemorySize, GEMM_SMEM);
    cudaFuncSetAttribute(gemm_mma<true, true, false>,
                         cudaFuncAttributeMaxDynamicSharedMemorySize, GEMM_SMEM);

    const size_t BU = (size_t)B_ * U_;
    const float qscale = 0.08838834764831845f;  // 1/sqrt(128)

    float* out_agent_policy = out;
    float* out_agent_value  = out + (size_t)B_ * A_;
    float* out_opp_policy   = out_agent_value + B_;
    float* out_opp_value    = out_opp_policy + (size_t)B_ * O_ * A_;
    float* out_infl         = out_opp_value + (size_t)B_ * O_;

    // converts
    {
        int n4 = (int)((size_t)B_ * F_ / 4);
        convert_split_h<<<(n4 + 255) / 256, 256>>>(features, feat_hi, feat_lo, n4);
    }
    auto convw = [](const float* s, h16* w, size_t n) {
        int n4 = (int)(n / 4);
        convert_w<<<(n4 + 255) / 256, 256>>>(s, w, n4);
    };
    convw(W_al, Wal, (size_t)U_ * F_);
    convw(W_in, Win, (size_t)3 * U_ * U_);
    convw(W_out, Wout, (size_t)U_ * U_);
    convw(W_ah, Wah, (size_t)U_ * 2 * U_);
    convw(W_ol, Wol, (size_t)O_ * U_ * F_);
    convw(W_oh, Woh, (size_t)O_ * U_ * U_);

    const dim3 gb(256);

    // 1) agent_latent -> cat[:, :U]
    gemm_mma<true, false, true><<<dim3(4, 64, 1), gb, GEMM_SMEM>>>(
        feat_hi, feat_lo, F_, 0ull, Wal, F_, 0ull, b_al, 0, 1.f,
        nullptr, 0, 0ull, cat_hi, cat_lo, 2 * U_, 0ull, F_);
    // 2) opp_lat (z=3)
    gemm_mma<true, false, true><<<dim3(4, 64, 3), gb, GEMM_SMEM>>>(
        feat_hi, feat_lo, F_, 0ull,
        Wol, F_, (unsigned long long)U_ * F_, b_ol, U_, 1.f,
        nullptr, 0, 0ull, opp_hi, opp_lo, U_, (unsigned long long)BU, F_);
    // 3) q (pre-scaled)
    gemm_mma<false, true, false><<<dim3(4, 64, 1), gb, GEMM_SMEM>>>(
        cat_hi, cat_lo, 2 * U_, 0ull, Win, U_, 0ull, b_in, 0, qscale,
        q, U_, 0ull, nullptr, nullptr, 0, 0ull, U_);
    // 4) k+v fused (N=1024), z=3 over opponents
    gemm_mma<false, true, false><<<dim3(8, 64, 3), gb, GEMM_SMEM>>>(
        opp_hi, opp_lo, U_, (unsigned long long)BU,
        Win + (size_t)U_ * U_, U_, 0ull, b_in + U_, 0, 1.f,
        kv, 2 * U_, (unsigned long long)B_ * 2 * U_,
        nullptr, nullptr, 0, 0ull, U_);
    // 5) attention
    attention_kernel<<<B_, 128>>>(q, kv, attn_hi, attn_lo, out_infl);
    // 6) attn_out -> cat[:, U:]
    gemm_mma<false, false, true><<<dim3(4, 64, 1), gb, GEMM_SMEM>>>(
        attn_hi, attn_lo, U_, 0ull, Wout, U_, 0ull, b_out, 0, 1.f,
        nullptr, 0, 0ull, cat_hi + U_, cat_lo + U_, 2 * U_, 0ull, U_);
    // 7) agent_head
    gemm_mma<true, true, false><<<dim3(4, 64, 1), gb, GEMM_SMEM>>>(
        cat_hi, cat_lo, 2 * U_, 0ull, Wah, 2 * U_, 0ull, b_ah, 0, 1.f,
        ah, U_, 0ull, nullptr, nullptr, 0, 0ull, 2 * U_);
    // 8) agent policy + value (fused)
    skinny_agent<<<B_ / 8, 256>>>(ah, W_ap, b_ap, W_av, b_av,
                                  out_agent_policy, out_agent_value);
    // 9) opp_heads (z=3)
    gemm_mma<true, true, false><<<dim3(4, 64, 3), gb, GEMM_SMEM>>>(
        opp_hi, opp_lo, U_, (unsigned long long)BU,
        Woh, U_, (unsigned long long)U_ * U_, b_oh, U_, 1.f,
        oh, U_, (unsigned long long)BU, nullptr, nullptr, 0, 0ull, U_);
    // 10) opponent policies + values (fused)
    skinny_opp<<<dim3(B_ / 8, 3), 256>>>(oh, W_op, b_op, W_ov, b_ov,
                                         out_opp_policy, out_opp_value);
}

// round 6
// speedup vs baseline: 6.2731x; 1.4703x over previous
#include <cuda_runtime.h>
#include <cuda_fp16.h>
#include <math.h>
#include <stdint.h>

// Problem constants
#define B_ 8192
#define F_ 1024
#define U_ 512
#define O_ 3
#define A_ 6
#define H_ 4
#define HD_ 128

typedef __half h16;

// ===========================================================================
// Scratch (device globals)
// ===========================================================================
__device__ __align__(128) h16   g_feat[(size_t)B_ * F_];
__device__ __align__(128) h16   g_cat[(size_t)B_ * 2 * U_];     // [agent_latent | attn_out]
__device__ __align__(128) h16   g_opp[(size_t)O_ * B_ * U_];
__device__ __align__(128) h16   g_attn[(size_t)B_ * U_];
__device__ __align__(128) float g_q[(size_t)B_ * U_];
__device__ __align__(128) float g_kv[(size_t)O_ * B_ * 2 * U_]; // [O][B][k|v]
__device__ __align__(128) float g_ah[(size_t)B_ * U_];
__device__ __align__(128) float g_oh[(size_t)O_ * B_ * U_];
// weights (fp16)
__device__ __align__(128) h16 g_Wal[(size_t)U_ * F_];
__device__ __align__(128) h16 g_Win[(size_t)3 * U_ * U_];
__device__ __align__(128) h16 g_Wout[(size_t)U_ * U_];
__device__ __align__(128) h16 g_Wah[(size_t)U_ * 2 * U_];
__device__ __align__(128) h16 g_Wol[(size_t)O_ * U_ * F_];
__device__ __align__(128) h16 g_Woh[(size_t)O_ * U_ * U_];

// ===========================================================================
// PTX helpers
// ===========================================================================
__device__ __forceinline__ uint32_t smem_u32(const void* p) {
    uint32_t a;
    asm("{ .reg .u64 t; cvta.to.shared.u64 t, %1; cvt.u32.u64 %0, t; }"
        : "=r"(a) : "l"(p));
    return a;
}
__device__ __forceinline__ void cp16(uint32_t s, const void* g) {
    asm volatile("cp.async.cg.shared.global [%0], [%1], 16;" :: "r"(s), "l"(g));
}
#define CP_COMMIT() asm volatile("cp.async.commit_group;" ::: "memory")
#define CP_WAIT0()  asm volatile("cp.async.wait_group 0;" ::: "memory")
#define CP_WAIT1()  asm volatile("cp.async.wait_group 1;" ::: "memory")
#define CP_WAIT2()  asm volatile("cp.async.wait_group 2;" ::: "memory")

__device__ __forceinline__ void ldsm4(uint32_t* r, uint32_t addr) {
    asm volatile("ldmatrix.sync.aligned.m8n8.x4.shared.b16 {%0,%1,%2,%3}, [%4];"
                 : "=r"(r[0]), "=r"(r[1]), "=r"(r[2]), "=r"(r[3]) : "r"(addr));
}
__device__ __forceinline__ void mma_f16(float* c, const uint32_t* a, const uint32_t* b) {
    asm volatile("mma.sync.aligned.m16n8k16.row.col.f32.f16.f16.f32 "
                 "{%0,%1,%2,%3}, {%4,%5,%6,%7}, {%8,%9}, {%0,%1,%2,%3};"
                 : "+f"(c[0]), "+f"(c[1]), "+f"(c[2]), "+f"(c[3])
                 : "r"(a[0]), "r"(a[1]), "r"(a[2]), "r"(a[3]),
                   "r"(b[0]), "r"(b[1]));
}

// ===========================================================================
// fp32 -> fp16 convert
// ===========================================================================
__global__ void convert_h(const float* __restrict__ src, h16* __restrict__ w, int n4)
{
    int i = blockIdx.x * blockDim.x + threadIdx.x;
    if (i >= n4) return;
    float4 x = ((const float4*)src)[i];
    h16 h[4] = {__float2half_rn(x.x), __float2half_rn(x.y),
                __float2half_rn(x.z), __float2half_rn(x.w)};
    ((uint2*)w)[i] = *(uint2*)h;
}

// ===========================================================================
// 1-pass fp16 HMMA GEMM: C = act((A @ W^T + bias) * scale)
// CTA 128x128, 8 warps (4Mx2N, warp 32x64), K stage 32.
// 4-stage cp.async ring, occupancy 2.
// ===========================================================================
#define MT 128
#define NT 128
#define KB 32
#define RSTRIDE 80
#define COMP_BYTES (128 * RSTRIDE)       // 10240
#define OFF_A 0
#define OFF_W COMP_BYTES
#define STG_BYTES (2 * COMP_BYTES)       // 20480
#define NSTAGE 4
#define GEMM_SMEM (1024 + NSTAGE * STG_BYTES)   // 82944

__device__ __forceinline__ void load_stage_async(
    uint32_t st, int tid,
    const h16* __restrict__ A, int lda, int mtile,
    const h16* __restrict__ W, int ldw, int ntile, int k0)
{
#pragma unroll
    for (int i = 0; i < 2; i++) {
        int idx = tid + i * 256;        // 0..511
        int r = idx >> 2, c = idx & 3;
        uint32_t so = (uint32_t)(r * RSTRIDE + c * 16);
        cp16(st + OFF_A + so, A + (size_t)(mtile + r) * lda + k0 + c * 8);
        cp16(st + OFF_W + so, W + (size_t)(ntile + r) * ldw + k0 + c * 8);
    }
    CP_COMMIT();
}

template <bool ELU_, bool WF32, bool WH16>
__global__ void __launch_bounds__(256, 2)
gemm_mma(const h16* __restrict__ A, int lda, unsigned long long Az,
         const h16* __restrict__ W, int ldw, unsigned long long Wz,
         const float* __restrict__ bias, int bz, float scale,
         float* __restrict__ Cf, int ldcf, unsigned long long Cfz,
         h16* __restrict__ Ch, int ldcb, unsigned long long Cbz,
         int K)
{
    extern __shared__ __align__(128) char smem[];
    const int z = blockIdx.z;
    A += (size_t)z * Az;  W += (size_t)z * Wz;  bias += (size_t)z * bz;
    if (WF32) Cf += (size_t)z * Cfz;
    if (WH16) Ch += (size_t)z * Cbz;

    float* bias_s = (float*)smem;
    const uint32_t st0 = smem_u32(smem + 1024);

    const int tid = threadIdx.x, lane = tid & 31, wid = tid >> 5;
    const int wm = wid & 3, wn = wid >> 2;
    const int mtile = blockIdx.y * MT;
    const int ntile = blockIdx.x * NT;

    if (tid < NT) bias_s[tid] = bias[ntile + tid];

    float acc[2][8][4];
#pragma unroll
    for (int i = 0; i < 2; i++)
#pragma unroll
        for (int j = 0; j < 8; j++)
#pragma unroll
            for (int t = 0; t < 4; t++) acc[i][j][t] = 0.f;

    const int nc = K / KB;

    // prologue: 3 stages in flight
    load_stage_async(st0, tid, A, lda, mtile, W, ldw, ntile, 0);
    if (nc > 1)
        load_stage_async(st0 + STG_BYTES, tid, A, lda, mtile, W, ldw, ntile, KB);
    if (nc > 2)
        load_stage_async(st0 + 2 * STG_BYTES, tid, A, lda, mtile, W, ldw, ntile, 2 * KB);

    const uint32_t a_row = (uint32_t)(lane & 15);
    const uint32_t a_koff = (uint32_t)((lane >> 4) * 16);
    const uint32_t b_row = (uint32_t)(((lane >> 4) * 8) + (lane & 7));
    const uint32_t b_koff = (uint32_t)(((lane >> 3) & 1) * 16);

    int sidx = 0;
    for (int c = 0; c < nc; ++c) {
        const int rem = nc - c - 1;
        if (rem >= 2)      CP_WAIT2();
        else if (rem == 1) CP_WAIT1();
        else               CP_WAIT0();
        __syncthreads();
        if (c + 3 < nc) {
            int nidx = sidx + 3; if (nidx >= NSTAGE) nidx -= NSTAGE;
            load_stage_async(st0 + nidx * STG_BYTES, tid,
                             A, lda, mtile, W, ldw, ntile, (c + 3) * KB);
        }
        const uint32_t cur = st0 + sidx * STG_BYTES;
#pragma unroll
        for (int kc = 0; kc < 2; kc++) {
            uint32_t af[2][4], wf[4][4];
#pragma unroll
            for (int mt = 0; mt < 2; mt++) {
                uint32_t row = wm * 32 + mt * 16 + a_row;
                ldsm4(af[mt], cur + OFF_A + row * RSTRIDE + kc * 32 + a_koff);
            }
#pragma unroll
            for (int q = 0; q < 4; q++) {
                uint32_t row = wn * 64 + q * 16 + b_row;
                ldsm4(wf[q], cur + OFF_W + row * RSTRIDE + kc * 32 + b_koff);
            }
#pragma unroll
            for (int mt = 0; mt < 2; mt++)
#pragma unroll
                for (int q = 0; q < 4; q++)
#pragma unroll
                    for (int s = 0; s < 2; s++)
                        mma_f16(acc[mt][2 * q + s], af[mt], &wf[q][2 * s]);
        }
        if (++sidx >= NSTAGE) sidx = 0;
    }

    // ---------------- epilogue ----------------
    const int g = lane >> 2, tg = lane & 3;
#pragma unroll
    for (int mt = 0; mt < 2; mt++) {
        const int m0 = mtile + wm * 32 + mt * 16 + g;
#pragma unroll
        for (int n8 = 0; n8 < 8; n8++) {
            const int nl = wn * 64 + n8 * 8 + tg * 2;
            const int n = ntile + nl;
            const float b0 = bias_s[nl], b1 = bias_s[nl + 1];
            float x0 = (acc[mt][n8][0] + b0) * scale;
            float x1 = (acc[mt][n8][1] + b1) * scale;
            float y0 = (acc[mt][n8][2] + b0) * scale;
            float y1 = (acc[mt][n8][3] + b1) * scale;
            if (ELU_) {
                x0 = x0 > 0.f ? x0 : expm1f(x0);
                x1 = x1 > 0.f ? x1 : expm1f(x1);
                y0 = y0 > 0.f ? y0 : expm1f(y0);
                y1 = y1 > 0.f ? y1 : expm1f(y1);
            }
            if (WF32) {
                *(float2*)(Cf + (size_t)m0 * ldcf + n) = make_float2(x0, x1);
                *(float2*)(Cf + (size_t)(m0 + 8) * ldcf + n) = make_float2(y0, y1);
            }
            if (WH16) {
                union { h16 h[2]; uint32_t u; } p;
                p.h[0] = __float2half_rn(x0); p.h[1] = __float2half_rn(x1);
                *(uint32_t*)(Ch + (size_t)m0 * ldcb + n) = p.u;
                p.h[0] = __float2half_rn(y0); p.h[1] = __float2half_rn(y1);
                *(uint32_t*)(Ch + (size_t)(m0 + 8) * ldcb + n) = p.u;
            }
        }
    }
}

// ===========================================================================
// Attention (kv fused layout [O][B][1024])
// ===========================================================================
__global__ void attention_kernel(const float* __restrict__ q,
                                 const float* __restrict__ kv,
                                 h16* __restrict__ attn,
                                 float* __restrict__ infl)
{
    const int b = blockIdx.x;
    const int tid = threadIdx.x;
    const int h = tid >> 5;
    const int lane = tid & 31;
    __shared__ float sw[H_][O_];

    const size_t base = (size_t)b * U_ + (size_t)h * HD_;
    const float4 qv = *(const float4*)(q + base + lane * 4);

    float s[O_];
#pragma unroll
    for (int o = 0; o < O_; o++) {
        const size_t kb = ((size_t)o * B_ + b) * (2 * U_) + (size_t)h * HD_;
        const float4 kvv = *(const float4*)(kv + kb + lane * 4);
        float d = qv.x * kvv.x + qv.y * kvv.y + qv.z * kvv.z + qv.w * kvv.w;
#pragma unroll
        for (int off = 16; off > 0; off >>= 1)
            d += __shfl_xor_sync(0xffffffffu, d, off);
        s[o] = d;
    }
    const float m = fmaxf(s[0], fmaxf(s[1], s[2]));
    const float e0 = expf(s[0] - m), e1 = expf(s[1] - m), e2 = expf(s[2] - m);
    const float inv = 1.f / (e0 + e1 + e2);
    const float w[O_] = {e0 * inv, e1 * inv, e2 * inv};

    float4 a = make_float4(0.f, 0.f, 0.f, 0.f);
#pragma unroll
    for (int o = 0; o < O_; o++) {
        const size_t vb = ((size_t)o * B_ + b) * (2 * U_) + U_ + (size_t)h * HD_;
        const float4 vv = *(const float4*)(kv + vb + lane * 4);
        a.x = fmaf(w[o], vv.x, a.x);
        a.y = fmaf(w[o], vv.y, a.y);
        a.z = fmaf(w[o], vv.z, a.z);
        a.w = fmaf(w[o], vv.w, a.w);
    }
    {
        union { h16 h[4]; uint2 u; } uh;
        uh.h[0] = __float2half_rn(a.x); uh.h[1] = __float2half_rn(a.y);
        uh.h[2] = __float2half_rn(a.z); uh.h[3] = __float2half_rn(a.w);
        *(uint2*)(attn + base + lane * 4) = uh.u;
    }

    if (lane == 0) { sw[h][0] = w[0]; sw[h][1] = w[1]; sw[h][2] = w[2]; }
    __syncthreads();
    if (tid < O_)
        infl[(size_t)b * O_ + tid] =
            0.25f * (sw[0][tid] + sw[1][tid] + sw[2][tid] + sw[3][tid]);
}

// ===========================================================================
// Fused skinny heads — one warp per row
// ===========================================================================
__global__ void skinny_agent(const float* __restrict__ ah,
                             const float* __restrict__ Wp, const float* __restrict__ bp,
                             const float* __restrict__ Wv, const float* __restrict__ bv,
                             float* __restrict__ pol, float* __restrict__ val)
{
    const int wid = threadIdx.x >> 5, lane = threadIdx.x & 31;
    const int b = blockIdx.x * 8 + wid;
    const float4* x4 = (const float4*)(ah + (size_t)b * U_);
    float4 x[4];
#pragma unroll
    for (int j = 0; j < 4; j++) x[j] = x4[lane + 32 * j];
#pragma unroll
    for (int n = 0; n < 7; n++) {
        const float4* w4 = (const float4*)((n < 6) ? (Wp + (size_t)n * U_) : Wv);
        float d = 0.f;
#pragma unroll
        for (int j = 0; j < 4; j++) {
            float4 wv4 = w4[lane + 32 * j];
            d += x[j].x * wv4.x + x[j].y * wv4.y + x[j].z * wv4.z + x[j].w * wv4.w;
        }
#pragma unroll
        for (int off = 16; off > 0; off >>= 1) d += __shfl_xor_sync(~0u, d, off);
        if (lane == 0) {
            if (n < 6) pol[(size_t)b * A_ + n] = d + bp[n];
            else       val[b] = d + bv[0];
        }
    }
}

__global__ void skinny_opp(const float* __restrict__ oh,
                           const float* __restrict__ W_op, const float* __restrict__ b_op,
                           const float* __restrict__ W_ov, const float* __restrict__ b_ov,
                           float* __restrict__ pol, float* __restrict__ val)
{
    const int wid = threadIdx.x >> 5, lane = threadIdx.x & 31;
    const int b = blockIdx.x * 8 + wid;
    const int o = blockIdx.y;
    const float4* x4 = (const float4*)(oh + ((size_t)o * B_ + b) * U_);
    float4 x[4];
#pragma unroll
    for (int j = 0; j < 4; j++) x[j] = x4[lane + 32 * j];
    const float* Wp = W_op + (size_t)o * A_ * U_;
    const float* Wv = W_ov + (size_t)o * U_;
#pragma unroll
    for (int n = 0; n < 7; n++) {
        const float4* w4 = (const float4*)((n < 6) ? (Wp + (size_t)n * U_) : Wv);
        float d = 0.f;
#pragma unroll
        for (int j = 0; j < 4; j++) {
            float4 wv4 = w4[lane + 32 * j];
            d += x[j].x * wv4.x + x[j].y * wv4.y + x[j].z * wv4.z + x[j].w * wv4.w;
        }
#pragma unroll
        for (int off = 16; off > 0; off >>= 1) d += __shfl_xor_sync(~0u, d, off);
        if (lane == 0) {
            if (n < 6) pol[(size_t)b * (O_ * A_) + o * A_ + n] = d + b_op[o * A_ + n];
            else       val[(size_t)b * O_ + o] = d + b_ov[o];
        }
    }
}

// ===========================================================================
extern "C" void kernel_launch(void* const* d_in, const int* in_sizes, int n_in,
                              void* d_out, int out_size)
{
    const float* features = (const float*)d_in[0];
    const float* W_al = (const float*)d_in[1];
    const float* b_al = (const float*)d_in[2];
    const float* W_in = (const float*)d_in[3];
    const float* b_in = (const float*)d_in[4];
    const float* W_out = (const float*)d_in[5];
    const float* b_out = (const float*)d_in[6];
    const float* W_ah = (const float*)d_in[7];
    const float* b_ah = (const float*)d_in[8];
    const float* W_ap = (const float*)d_in[9];
    const float* b_ap = (const float*)d_in[10];
    const float* W_av = (const float*)d_in[11];
    const float* b_av = (const float*)d_in[12];
    const float* W_ol = (const float*)d_in[13];
    const float* b_ol = (const float*)d_in[14];
    const float* W_oh = (const float*)d_in[15];
    const float* b_oh = (const float*)d_in[16];
    const float* W_op = (const float*)d_in[17];
    const float* b_op = (const float*)d_in[18];
    const float* W_ov = (const float*)d_in[19];
    const float* b_ov = (const float*)d_in[20];
    float* out = (float*)d_out;

    h16 *feat, *cat, *opp, *attn, *Wal, *Win, *Wout, *Wah, *Wol, *Woh;
    float *q, *kv, *ah, *oh;
    cudaGetSymbolAddress((void**)&feat, g_feat);
    cudaGetSymbolAddress((void**)&cat, g_cat);
    cudaGetSymbolAddress((void**)&opp, g_opp);
    cudaGetSymbolAddress((void**)&attn, g_attn);
    cudaGetSymbolAddress((void**)&Wal, g_Wal);
    cudaGetSymbolAddress((void**)&Win, g_Win);
    cudaGetSymbolAddress((void**)&Wout, g_Wout);
    cudaGetSymbolAddress((void**)&Wah, g_Wah);
    cudaGetSymbolAddress((void**)&Wol, g_Wol);
    cudaGetSymbolAddress((void**)&Woh, g_Woh);
    cudaGetSymbolAddress((void**)&q, g_q);
    cudaGetSymbolAddress((void**)&kv, g_kv);
    cudaGetSymbolAddress((void**)&ah, g_ah);
    cudaGetSymbolAddress((void**)&oh, g_oh);

    cudaFuncSetAttribute(gemm_mma<true, false, true>,
                         cudaFuncAttributeMaxDynamicSharedMemorySize, GEMM_SMEM);
    cudaFuncSetAttribute(gemm_mma<false, true, false>,
                         cudaFuncAttributeMaxDynamicSharedMemorySize, GEMM_SMEM);
    cudaFuncSetAttribute(gemm_mma<false, false, true>,
                         cudaFuncAttributeMaxDynamicSharedMemorySize, GEMM_SMEM);
    cudaFuncSetAttribute(gemm_mma<true, true, false>,
                         cudaFuncAttributeMaxDynamicSharedMemorySize, GEMM_SMEM);

    const size_t BU = (size_t)B_ * U_;
    const float qscale = 0.08838834764831845f;  // 1/sqrt(128)

    float* out_agent_policy = out;
    float* out_agent_value  = out + (size_t)B_ * A_;
    float* out_opp_policy   = out_agent_value + B_;
    float* out_opp_value    = out_opp_policy + (size_t)B_ * O_ * A_;
    float* out_infl         = out_opp_value + (size_t)B_ * O_;

    auto convh = [](const float* s, h16* w, size_t n) {
        int n4 = (int)(n / 4);
        convert_h<<<(n4 + 255) / 256, 256>>>(s, w, n4);
    };
    convh(features, feat, (size_t)B_ * F_);
    convh(W_al, Wal, (size_t)U_ * F_);
    convh(W_in, Win, (size_t)3 * U_ * U_);
    convh(W_out, Wout, (size_t)U_ * U_);
    convh(W_ah, Wah, (size_t)U_ * 2 * U_);
    convh(W_ol, Wol, (size_t)O_ * U_ * F_);
    convh(W_oh, Woh, (size_t)O_ * U_ * U_);

    const dim3 gb(256);

    // 1) agent_latent -> cat[:, :U]
    gemm_mma<true, false, true><<<dim3(4, 64, 1), gb, GEMM_SMEM>>>(
        feat, F_, 0ull, Wal, F_, 0ull, b_al, 0, 1.f,
        nullptr, 0, 0ull, cat, 2 * U_, 0ull, F_);
    // 2) opp_lat (z=3)
    gemm_mma<true, false, true><<<dim3(4, 64, 3), gb, GEMM_SMEM>>>(
        feat, F_, 0ull, Wol, F_, (unsigned long long)U_ * F_, b_ol, U_, 1.f,
        nullptr, 0, 0ull, opp, U_, (unsigned long long)BU, F_);
    // 3) q (pre-scaled)
    gemm_mma<false, true, false><<<dim3(4, 64, 1), gb, GEMM_SMEM>>>(
        cat, 2 * U_, 0ull, Win, U_, 0ull, b_in, 0, qscale,
        q, U_, 0ull, nullptr, 0, 0ull, U_);
    // 4) k+v fused (N=1024), z=3
    gemm_mma<false, true, false><<<dim3(8, 64, 3), gb, GEMM_SMEM>>>(
        opp, U_, (unsigned long long)BU,
        Win + (size_t)U_ * U_, U_, 0ull, b_in + U_, 0, 1.f,
        kv, 2 * U_, (unsigned long long)B_ * 2 * U_, nullptr, 0, 0ull, U_);
    // 5) attention
    attention_kernel<<<B_, 128>>>(q, kv, attn, out_infl);
    // 6) attn_out -> cat[:, U:]
    gemm_mma<false, false, true><<<dim3(4, 64, 1), gb, GEMM_SMEM>>>(
        attn, U_, 0ull, Wout, U_, 0ull, b_out, 0, 1.f,
        nullptr, 0, 0ull, cat + U_, 2 * U_, 0ull, U_);
    // 7) agent_head
    gemm_mma<true, true, false><<<dim3(4, 64, 1), gb, GEMM_SMEM>>>(
        cat, 2 * U_, 0ull, Wah, 2 * U_, 0ull, b_ah, 0, 1.f,
        ah, U_, 0ull, nullptr, 0, 0ull, 2 * U_);
    // 8) agent policy + value
    skinny_agent<<<B_ / 8, 256>>>(ah, W_ap, b_ap, W_av, b_av,
                                  out_agent_policy, out_agent_value);
    // 9) opp_heads (z=3)
    gemm_mma<true, true, false><<<dim3(4, 64, 3), gb, GEMM_SMEM>>>(
        opp, U_, (unsigned long long)BU,
        Woh, U_, (unsigned long long)U_ * U_, b_oh, U_, 1.f,
        oh, U_, (unsigned long long)BU, nullptr, 0, 0ull, U_);
    // 10) opponent policies + values
    skinny_opp<<<dim3(B_ / 8, 3), 256>>>(oh, W_op, b_op, W_ov, b_ov,
                                         out_opp_policy, out_opp_value);
}